// round 12
// baseline (speedup 1.0000x reference)
#include <cuda_runtime.h>

// ---------------- problem constants ----------------
#define Ln   256
#define Cn   64
#define NUMn 64
#define Bn   32
#define NT   256
#define SA   68    // row stride (floats): 272B % 128 == 16 -> conflict-free LDS.128 phases
#define SV   260   // row stride (floats) for c-major K/V tiles: 1040B % 128 == 16
#define SP   132   // row stride (floats) for P/Q region: 528B % 128 == 16

#define SZ (33554432ULL)  // B*NUM*L*C per tensor

// gmem scratch (device globals = sanctioned scratch)
__device__ float g_rawQ[SZ];    // raw q, normal [b][t][l][c]
__device__ float g_rawKT[SZ];   // raw k, c-major [b][t][c][l]
__device__ float g_rawQT[SZ];   // raw q, c-major
__device__ float g_rawVT[SZ];   // raw v, c-major
__device__ float g_KT[SZ];      // shadow of output K, c-major
__device__ float g_WT[6 * 4096];// fk1,fk2,fq1,fq2,fx1,fx2 transposed [c][d]

// ---------------- shared memory layout (floats) ----------------
// OFF_A (17408 fl): Kt[64][SV] -> Vt[64][SV] -> {z,h,W1t,W2t}[64][SA] each
#define OFF_A  0
#define OFF_Z  (OFF_A)
#define OFF_H  (OFF_A + 64*SA)
#define OFF_W1 (OFF_A + 128*SA)
#define OFF_W2 (OFF_A + 192*SA)
#define OFF_P  (OFF_A + 256*SA)   // 64*SP = 8448 fl: Q staging [RB][SP] -> P 128-col chunk
#define OFF_C  (OFF_P + 64*SP)
#define C_G0   (OFF_C + 0)
#define C_B0   (OFF_C + 64)
#define C_G1   (OFF_C + 128)
#define C_B1   (OFF_C + 192)
#define C_F1B  (OFF_C + 256)
#define C_F2B  (OFF_C + 320)
#define SMEM_FLOATS (OFF_C + 384)
#define SMEM_BYTES  (SMEM_FLOATS * 4)   // 104,960 B -> 2 CTAs/SM

typedef unsigned long long u64t;

__device__ __forceinline__ u64t fma2(u64t a, u64t b, u64t c) {
  u64t d; asm("fma.rn.f32x2 %0, %1, %2, %3;" : "=l"(d) : "l"(a), "l"(b), "l"(c)); return d;
}
__device__ __forceinline__ u64t pack2(float x, float y) {
  u64t d; asm("mov.b64 %0, {%1, %2};" : "=l"(d) : "f"(x), "f"(y)); return d;
}
__device__ __forceinline__ float2 unpack2(u64t v) {
  float2 r; asm("mov.b64 {%0, %1}, %2;" : "=f"(r.x), "=f"(r.y) : "l"(v)); return r;
}
__device__ __forceinline__ float f4c(const float4& v, int k) {
  return (k == 0) ? v.x : (k == 1) ? v.y : (k == 2) ? v.z : v.w;
}

struct AttnParams {
  const float *g0x, *b0x, *g1x, *b1x;
  const float *g0k, *b0k, *g1k, *b1k;
  const float *g0q, *b0q, *g1q, *b1q;
  const float *fx1b, *fx2b, *fk1b, *fk2b, *fq1b, *fq2b;
  float *K, *Q, *V;
  int t;
};

__device__ __forceinline__ float hmax16(float v) {
  v = fmaxf(v, __shfl_xor_sync(0xffffffffu, v, 1));
  v = fmaxf(v, __shfl_xor_sync(0xffffffffu, v, 2));
  v = fmaxf(v, __shfl_xor_sync(0xffffffffu, v, 4));
  v = fmaxf(v, __shfl_xor_sync(0xffffffffu, v, 8));
  return v;
}
__device__ __forceinline__ float hsum16(float v) {
  v += __shfl_xor_sync(0xffffffffu, v, 1);
  v += __shfl_xor_sync(0xffffffffu, v, 2);
  v += __shfl_xor_sync(0xffffffffu, v, 4);
  v += __shfl_xor_sync(0xffffffffu, v, 8);
  return v;
}

// coalesced row-copy: gmem [64][256] (c-major) -> smem [64][SV]
__device__ __forceinline__ void load_cmajor_64x256(float* dst, const float* __restrict__ src, int tid) {
  const float4* s4 = (const float4*)src;
  #pragma unroll
  for (int it = 0; it < 16; it++) {
    int i = tid + it * NT;          // 0..4095
    int r = i >> 6, c4 = (i & 63) << 2;
    *(float4*)(dst + r * SV + c4) = __ldg(s4 + i);
  }
}

// coalesced row-copy: gmem [64][64] -> smem [64][SA]
__device__ __forceinline__ void load_cmajor_64x64(float* dst, const float* __restrict__ src, int tid) {
  const float4* s4 = (const float4*)src;
  #pragma unroll
  for (int it = 0; it < 4; it++) {
    int i = tid + it * NT;          // 0..1023
    int r = i >> 4, c4 = (i & 15) << 2;
    *(float4*)(dst + r * SA + c4) = __ldg(s4 + i);
  }
}

// ============ one-time: transpose the 6 FFN weight matrices into g_WT ============
__global__ __launch_bounds__(NT)
void transpose_w_kernel(const float* s0, const float* s1, const float* s2,
                        const float* s3, const float* s4, const float* s5) {
  __shared__ float tile[64][65];
  const float* srcs[6] = {s0, s1, s2, s3, s4, s5};
  const float* src = srcs[blockIdx.x];
  float* dst = g_WT + blockIdx.x * 4096;
  const int tid = threadIdx.x;
  for (int i = tid; i < 4096; i += NT) tile[i >> 6][i & 63] = __ldg(src + i);
  __syncthreads();
  for (int i = tid; i < 4096; i += NT) dst[i] = tile[i & 63][i >> 6];
}

// ============ precompute: raw projections of (x+emb); transposed variants; K/Q/V & KT at t=0 ====
// grid = Bn*NUMn*8; block covers one (b,t) 32-row slab (l0..l0+31) x 8 heads
__global__ __launch_bounds__(NT)
void precompute_raw_kernel(const float* __restrict__ x, const float* __restrict__ emb,
                           const float* __restrict__ Wk, const float* __restrict__ bk,
                           const float* __restrict__ Wq, const float* __restrict__ bq,
                           const float* __restrict__ Wv, const float* __restrict__ bv,
                           float* __restrict__ K, float* __restrict__ Q, float* __restrict__ V) {
  __shared__ float w[3 * 512 + 3 * 64];
  __shared__ float tr[3][64][33];
  const int tid = threadIdx.x;
  for (int i = tid; i < 512; i += NT) {
    w[i]        = __ldg(Wk + i);
    w[512 + i]  = __ldg(Wq + i);
    w[1024 + i] = __ldg(Wv + i);
  }
  if (tid < 64) {
    w[1536 + tid] = __ldg(bk + tid);
    w[1600 + tid] = __ldg(bq + tid);
    w[1664 + tid] = __ldg(bv + tid);
  }
  __syncthreads();

  const int bidx  = blockIdx.x;
  const int btIdx = bidx >> 3;          // b*64 + t
  const int l0    = (bidx & 7) << 5;
  const int t     = btIdx & 63;
  const int h  = tid & 7;
  const int dl = tid >> 3;              // 0..31
  const int l  = l0 + dl;
  const size_t row = (size_t)btIdx * 256 + l;

  float xe[8];
  const float* xr = x + row * 64 + h * 8;
  const float* er = emb + l * 64 + h * 8;
  #pragma unroll
  for (int d = 0; d < 8; d++) xe[d] = __ldg(xr + d) + __ldg(er + d);

  float* outs0[3] = {K, Q, V};
  #pragma unroll
  for (int pidx = 0; pidx < 3; pidx++) {
    const float* W  = w + pidx * 512 + h * 64;
    const float* bb = w + 1536 + pidx * 64 + h * 8;
    float acc[8];
    #pragma unroll
    for (int e = 0; e < 8; e++) acc[e] = bb[e];
    #pragma unroll
    for (int d = 0; d < 8; d++) {
      float xv = xe[d];
      #pragma unroll
      for (int e = 0; e < 8; e++) acc[e] = fmaf(xv, W[d * 8 + e], acc[e]);
    }
    #pragma unroll
    for (int e = 0; e < 8; e++) tr[pidx][h * 8 + e][dl] = acc[e];
    if (pidx == 1) {
      float* dq = g_rawQ + row * 64 + h * 8;
      #pragma unroll
      for (int e = 0; e < 8; e++) dq[e] = acc[e];
    }
    if (t == 0) {
      float* d2 = outs0[pidx] + row * 64 + h * 8;
      #pragma unroll
      for (int e = 0; e < 8; e++) d2[e] = acc[e];
    }
  }
  __syncthreads();

  // coalesced transposed writes: [c][l] slab
  const size_t base = (size_t)btIdx * 16384;
  for (int j = tid; j < 2048; j += NT) {
    int c = j >> 5, d = j & 31;
    size_t off = base + (size_t)c * 256 + l0 + d;
    g_rawKT[off] = tr[0][c][d];
    g_rawQT[off] = tr[1][c][d];
    g_rawVT[off] = tr[2][c][d];
    if (t == 0) g_KT[off] = tr[0][c][d];
  }
}

// ============ attention body (RPT rows per thread; RB = 16*RPT rows per CTA) ============
// mode 0: k-attn  keysT=rawKT[t], valsT=rawKT[t], queries=Q[t-1]   -> K[t] (+ KT shadow)
// mode 1: q-attn  keysT=KT[t-1],  valsT=rawQT[t], queries=rawQ[t]  -> Q[t]
// mode 2: v-attn  keysT=KT[t],    valsT=rawVT[t], queries=Q[t]     -> V[t]
template <int RPT>
__device__ __forceinline__ void attn_body(const AttnParams& p, int mode, int t, int rb, float* sm) {
  const int tid = threadIdx.x;
  const int b   = blockIdx.y;

  const size_t bOff    = (size_t)b * NUMn * Ln * Cn;
  const size_t curOff  = bOff + (size_t)t * Ln * Cn;
  const size_t prevOff = bOff + (size_t)(t - 1) * Ln * Cn;

  const float *g0, *b0, *g1, *b1, *fb1, *fb2;
  const float *keysT, *qG, *valsT, *w1, *w2;
  float* outG;
  if (mode == 0) {
    g0 = p.g0k; b0 = p.b0k; g1 = p.g1k; b1 = p.b1k;
    fb1 = p.fk1b; fb2 = p.fk2b;
    w1 = g_WT + 0 * 4096; w2 = g_WT + 1 * 4096;
    keysT = g_rawKT + curOff; valsT = g_rawKT + curOff;
    qG = p.Q + prevOff + (size_t)rb * Cn;
    outG = p.K + curOff;
  } else if (mode == 1) {
    g0 = p.g0q; b0 = p.b0q; g1 = p.g1q; b1 = p.b1q;
    fb1 = p.fq1b; fb2 = p.fq2b;
    w1 = g_WT + 2 * 4096; w2 = g_WT + 3 * 4096;
    keysT = g_KT + prevOff; valsT = g_rawQT + curOff;
    qG = g_rawQ + curOff + (size_t)rb * Cn;
    outG = p.Q + curOff;
  } else {
    g0 = p.g0x; b0 = p.b0x; g1 = p.g1x; b1 = p.b1x;
    fb1 = p.fx1b; fb2 = p.fx2b;
    w1 = g_WT + 4 * 4096; w2 = g_WT + 5 * 4096;
    keysT = g_KT + curOff; valsT = g_rawVT + curOff;
    qG = p.Q + curOff + (size_t)rb * Cn;
    outG = p.V + curOff;
  }

  // ---- load Kt (c-major row copy), Q rows (stride SP), consts ----
  load_cmajor_64x256(sm + OFF_A, keysT, tid);
  {
    const float4* q4 = (const float4*)qG;
    #pragma unroll
    for (int it = 0; it < RPT; it++) {
      int i = tid + it * NT;
      float4 v = __ldg(q4 + i);
      int l = i >> 4, c = (i & 15) << 2;
      *(float4*)(sm + OFF_P + l * SP + c) = v;
    }
    if (tid < 64) {
      sm[C_G0  + tid] = __ldg(g0 + tid);
      sm[C_B0  + tid] = __ldg(b0 + tid);
      sm[C_G1  + tid] = __ldg(g1 + tid);
      sm[C_B1  + tid] = __ldg(b1 + tid);
      sm[C_F1B + tid] = __ldg(fb1 + tid);
      sm[C_F2B + tid] = __ldg(fb2 + tid);
    }
  }
  __syncthreads();

  const int rg = tid >> 4;   // 16 row-groups, RPT rows each
  const int cg = tid & 15;   // thread owns S cols 4*cg + 64*q + e  (q=0..3, e=0..3)

  // ---- S = Q @ Kt (RB x 256, k=64), packed f32x2 along n ----
  u64t acc[RPT][4][2];
  #pragma unroll
  for (int i = 0; i < RPT; i++)
    #pragma unroll
    for (int q = 0; q < 4; q++) { acc[i][q][0] = 0ull; acc[i][q][1] = 0ull; }
  {
    const float* qb = sm + OFF_P + (rg * RPT) * SP;
    #pragma unroll 4
    for (int d4 = 0; d4 < 64; d4 += 4) {
      float4 qv[RPT];
      #pragma unroll
      for (int i = 0; i < RPT; i++) qv[i] = *(const float4*)(qb + i * SP + d4);
      #pragma unroll
      for (int dd = 0; dd < 4; dd++) {
        u64t qp[RPT];
        #pragma unroll
        for (int i = 0; i < RPT; i++) { float s = f4c(qv[i], dd); qp[i] = pack2(s, s); }
        const float* kt = sm + OFF_A + (d4 + dd) * SV + 4 * cg;
        #pragma unroll
        for (int q = 0; q < 4; q++) {
          ulonglong2 kv = *(const ulonglong2*)(kt + 64 * q);
          #pragma unroll
          for (int i = 0; i < RPT; i++) {
            acc[i][q][0] = fma2(qp[i], kv.x, acc[i][q][0]);
            acc[i][q][1] = fma2(qp[i], kv.y, acc[i][q][1]);
          }
        }
      }
    }
  }
  __syncthreads();  // Kt + Q reads done; A region free

  // ---- load Vt into A (c-major row copy; LDG latency overlaps softmax) ----
  load_cmajor_64x256(sm + OFF_A, valsT, tid);

  // ---- softmax in registers, fold /sqrt(64) ----
  float pv[RPT][16];
  #pragma unroll
  for (int i = 0; i < RPT; i++) {
    #pragma unroll
    for (int q = 0; q < 4; q++) {
      float2 e0 = unpack2(acc[i][q][0]);
      float2 e1 = unpack2(acc[i][q][1]);
      pv[i][q * 4 + 0] = e0.x; pv[i][q * 4 + 1] = e0.y;
      pv[i][q * 4 + 2] = e1.x; pv[i][q * 4 + 3] = e1.y;
    }
    float m = pv[i][0];
    #pragma unroll
    for (int j = 1; j < 16; j++) m = fmaxf(m, pv[i][j]);
    m = hmax16(m);
    float s = 0.f;
    #pragma unroll
    for (int j = 0; j < 16; j++) {
      float e = __expf(pv[i][j] - m);
      pv[i][j] = e;
      s += e;
    }
    s = hsum16(s);
    float sc = 0.125f / s;
    #pragma unroll
    for (int j = 0; j < 16; j++) pv[i][j] *= sc;
  }

  // ---- O = P @ V, k in 2 chunks of 128 via smem P tile (dead Q region) ----
  u64t acc2[RPT][4];
  #pragma unroll
  for (int i = 0; i < RPT; i++)
    #pragma unroll
    for (int c2 = 0; c2 < 4; c2++) acc2[i][c2] = 0ull;
  #pragma unroll
  for (int ch = 0; ch < 2; ch++) {
    __syncthreads();  // ch0: Vt stores + Q reads complete; ch1: chunk-0 reads complete
    #pragma unroll
    for (int i = 0; i < RPT; i++) {
      float* pr = sm + OFF_P + (rg * RPT + i) * SP;
      *(float4*)(pr + 4 * cg) =
          make_float4(pv[i][(2*ch)*4 + 0], pv[i][(2*ch)*4 + 1], pv[i][(2*ch)*4 + 2], pv[i][(2*ch)*4 + 3]);
      *(float4*)(pr + 64 + 4 * cg) =
          make_float4(pv[i][(2*ch+1)*4 + 0], pv[i][(2*ch+1)*4 + 1], pv[i][(2*ch+1)*4 + 2], pv[i][(2*ch+1)*4 + 3]);
    }
    __syncthreads();  // chunk visible
    const float* pb = sm + OFF_P + (rg * RPT) * SP;
    const float* vb = sm + OFF_A + cg * SV + ch * 128;
    #pragma unroll 4
    for (int m4 = 0; m4 < 128; m4 += 4) {
      ulonglong2 pp[RPT];
      #pragma unroll
      for (int i = 0; i < RPT; i++) pp[i] = *(const ulonglong2*)(pb + i * SP + m4);
      #pragma unroll
      for (int c2 = 0; c2 < 4; c2++) {
        ulonglong2 vv = *(const ulonglong2*)(vb + c2 * (16 * SV) + m4);
        #pragma unroll
        for (int i = 0; i < RPT; i++) {
          acc2[i][c2] = fma2(pp[i].x, vv.x, acc2[i][c2]);
          acc2[i][c2] = fma2(pp[i].y, vv.y, acc2[i][c2]);
        }
      }
    }
  }

  // ---- residual (+v at query row) + LayerNorm 1 ----
  float z[RPT][4];
  {
    float sum[RPT], sq[RPT];
    #pragma unroll
    for (int i = 0; i < RPT; i++) { sum[i] = 0.f; sq[i] = 0.f; }
    #pragma unroll
    for (int i = 0; i < RPT; i++) {
      int n = rb + rg * RPT + i;
      #pragma unroll
      for (int c2 = 0; c2 < 4; c2++) {
        float2 tacc = unpack2(acc2[i][c2]);
        float o = tacc.x + tacc.y + sm[OFF_A + (cg + 16 * c2) * SV + n];
        z[i][c2] = o;
        sum[i] += o;
        sq[i]  += o * o;
      }
    }
    #pragma unroll
    for (int i = 0; i < RPT; i++) { sum[i] = hsum16(sum[i]); sq[i] = hsum16(sq[i]); }
    #pragma unroll
    for (int i = 0; i < RPT; i++) {
      float mean = sum[i] * (1.f / 64.f);
      float var  = sq[i] * (1.f / 64.f) - mean * mean;
      float rs = rsqrtf(var + 1e-5f);
      #pragma unroll
      for (int c2 = 0; c2 < 4; c2++) {
        int c = cg + 16 * c2;
        z[i][c2] = (z[i][c2] - mean) * rs * sm[C_G0 + c] + sm[C_B0 + c];
      }
    }
  }
  __syncthreads();  // Vt + P dead; A region free

  // ---- stage z; load W1t,W2t (pre-transposed, coalesced) ----
  #pragma unroll
  for (int i = 0; i < RPT; i++)
    #pragma unroll
    for (int c2 = 0; c2 < 4; c2++)
      sm[OFF_Z + (rg * RPT + i) * SA + cg + 16 * c2] = z[i][c2];
  load_cmajor_64x64(sm + OFF_W1, w1, tid);
  load_cmajor_64x64(sm + OFF_W2, w2, tid);
  __syncthreads();

  // ---- FFN layer 1: h = relu(z @ W1 + b1), packed f32x2 along k ----
  {
    u64t hacc[RPT][4];
    #pragma unroll
    for (int i = 0; i < RPT; i++)
      #pragma unroll
      for (int c2 = 0; c2 < 4; c2++) hacc[i][c2] = 0ull;
    const float* zb = sm + OFF_Z + (rg * RPT) * SA;
    const float* wb = sm + OFF_W1 + cg * SA;
    #pragma unroll 4
    for (int d4 = 0; d4 < 64; d4 += 4) {
      ulonglong2 zz[RPT];
      #pragma unroll
      for (int i = 0; i < RPT; i++) zz[i] = *(const ulonglong2*)(zb + i * SA + d4);
      #pragma unroll
      for (int c2 = 0; c2 < 4; c2++) {
        ulonglong2 ww = *(const ulonglong2*)(wb + c2 * (16 * SA) + d4);
        #pragma unroll
        for (int i = 0; i < RPT; i++) {
          hacc[i][c2] = fma2(zz[i].x, ww.x, hacc[i][c2]);
          hacc[i][c2] = fma2(zz[i].y, ww.y, hacc[i][c2]);
        }
      }
    }
    #pragma unroll
    for (int i = 0; i < RPT; i++)
      #pragma unroll
      for (int c2 = 0; c2 < 4; c2++) {
        float2 th = unpack2(hacc[i][c2]);
        float hv = th.x + th.y + sm[C_F1B + cg + 16 * c2];
        sm[OFF_H + (rg * RPT + i) * SA + cg + 16 * c2] = fmaxf(hv, 0.f);
      }
  }
  __syncthreads();

  // ---- FFN layer 2 + residual + LayerNorm 2 + store (+KT shadow for mode 0) ----
  {
    u64t facc[RPT][4];
    #pragma unroll
    for (int i = 0; i < RPT; i++)
      #pragma unroll
      for (int c2 = 0; c2 < 4; c2++) facc[i][c2] = 0ull;
    const float* hb = sm + OFF_H + (rg * RPT) * SA;
    const float* wb = sm + OFF_W2 + cg * SA;
    #pragma unroll 4
    for (int d4 = 0; d4 < 64; d4 += 4) {
      ulonglong2 hh[RPT];
      #pragma unroll
      for (int i = 0; i < RPT; i++) hh[i] = *(const ulonglong2*)(hb + i * SA + d4);
      #pragma unroll
      for (int c2 = 0; c2 < 4; c2++) {
        ulonglong2 ww = *(const ulonglong2*)(wb + c2 * (16 * SA) + d4);
        #pragma unroll
        for (int i = 0; i < RPT; i++) {
          facc[i][c2] = fma2(hh[i].x, ww.x, facc[i][c2]);
          facc[i][c2] = fma2(hh[i].y, ww.y, facc[i][c2]);
        }
      }
    }
    float f[RPT][4];
    float sum[RPT], sq[RPT];
    #pragma unroll
    for (int i = 0; i < RPT; i++) { sum[i] = 0.f; sq[i] = 0.f; }
    #pragma unroll
    for (int i = 0; i < RPT; i++)
      #pragma unroll
      for (int c2 = 0; c2 < 4; c2++) {
        float2 tf = unpack2(facc[i][c2]);
        float o = tf.x + tf.y + sm[C_F2B + cg + 16 * c2] + z[i][c2];
        f[i][c2] = o;
        sum[i] += o;
        sq[i]  += o * o;
      }
    #pragma unroll
    for (int i = 0; i < RPT; i++) { sum[i] = hsum16(sum[i]); sq[i] = hsum16(sq[i]); }
    float* ktG = g_KT + curOff;
    #pragma unroll
    for (int i = 0; i < RPT; i++) {
      float mean = sum[i] * (1.f / 64.f);
      float var  = sq[i] * (1.f / 64.f) - mean * mean;
      float rs = rsqrtf(var + 1e-5f);
      int n = rb + rg * RPT + i;
      float* orow = outG + (size_t)n * Cn;
      #pragma unroll
      for (int c2 = 0; c2 < 4; c2++) {
        int c = cg + 16 * c2;
        float val = (f[i][c2] - mean) * rs * sm[C_G1 + c] + sm[C_B1 + c];
        orow[c] = val;
        if (mode == 0) ktG[c * 256 + n] = val;   // transposed shadow of K
      }
    }
  }
}

// job 0: A(t)            grid (8,32): bx 0-3 mode0, 4-7 mode1, RPT=4
// job 1: B(t) + A(t+1)   grid (16,32): bx 0-7 -> A(t+1) (RPT=4); bx 8-15 -> B(t) (RPT=2)
// job 2: B(t)            grid (8,32): mode 2 at t, RPT=2
__global__ __launch_bounds__(NT, 2)
void attn_step_kernel(AttnParams p, int job) {
  extern __shared__ float sm[];
  const int bx = (int)blockIdx.x;
  if (job == 1) {
    if (bx < 8) attn_body<4>(p, bx >> 2, p.t + 1, (bx & 3) * 64, sm);
    else        attn_body<2>(p, 2, p.t, (bx - 8) * 32, sm);
  } else if (job == 0) {
    attn_body<4>(p, bx >> 2, p.t, (bx & 3) * 64, sm);
  } else {
    attn_body<2>(p, 2, p.t, bx * 32, sm);
  }
}

extern "C" void kernel_launch(void* const* d_in, const int* in_sizes, int n_in,
                              void* d_out, int out_size) {
  (void)in_sizes; (void)n_in; (void)out_size;
  const float* x   = (const float*)d_in[0];
  const float* emb = (const float*)d_in[1];
  const float* Wk  = (const float*)d_in[2];
  const float* bk  = (const float*)d_in[3];
  const float* Wq  = (const float*)d_in[4];
  const float* bq  = (const float*)d_in[5];
  const float* Wv  = (const float*)d_in[6];
  const float* bv  = (const float*)d_in[7];

  AttnParams p;
  p.g0x  = (const float*)d_in[8];   p.b0x = (const float*)d_in[9];
  p.g1x  = (const float*)d_in[10];  p.b1x = (const float*)d_in[11];
  p.g0k  = (const float*)d_in[12];  p.b0k = (const float*)d_in[13];
  p.g1k  = (const float*)d_in[14];  p.b1k = (const float*)d_in[15];
  p.g0q  = (const float*)d_in[16];  p.b0q = (const float*)d_in[17];
  p.g1q  = (const float*)d_in[18];  p.b1q = (const float*)d_in[19];
  const float* fx1w = (const float*)d_in[20];  p.fx1b = (const float*)d_in[21];
  const float* fx2w = (const float*)d_in[22];  p.fx2b = (const float*)d_in[23];
  const float* fk1w = (const float*)d_in[24];  p.fk1b = (const float*)d_in[25];
  const float* fk2w = (const float*)d_in[26];  p.fk2b = (const float*)d_in[27];
  const float* fq1w = (const float*)d_in[28];  p.fq1b = (const float*)d_in[29];
  const float* fq2w = (const float*)d_in[30];  p.fq2b = (const float*)d_in[31];

  float* out = (float*)d_out;
  p.K = out;
  p.Q = out + SZ;
  p.V = out + 2 * SZ;

  cudaFuncSetAttribute((const void*)attn_step_kernel,
                       cudaFuncAttributeMaxDynamicSharedMemorySize, SMEM_BYTES);

  // one-time prep: transposed FFN weights + raw projections (+t=0 outputs/shadow)
  transpose_w_kernel<<<6, NT>>>(fk1w, fk2w, fq1w, fq2w, fx1w, fx2w);
  precompute_raw_kernel<<<Bn * NUMn * 8, NT>>>(x, emb, Wk, bk, Wq, bq, Wv, bv,
                                               p.K, p.Q, p.V);

  // A(1)
  p.t = 1;
  attn_step_kernel<<<dim3(8, Bn), NT, SMEM_BYTES>>>(p, 0);
  // merged B(t) + A(t+1), t = 1..62
  for (int t = 1; t <= 62; t++) {
    p.t = t;
    attn_step_kernel<<<dim3(16, Bn), NT, SMEM_BYTES>>>(p, 1);
  }
  // B(63)
  p.t = 63;
  attn_step_kernel<<<dim3(8, Bn), NT, SMEM_BYTES>>>(p, 2);
}

// round 13
// speedup vs baseline: 1.2551x; 1.2551x over previous
#include <cuda_runtime.h>

// ---------------- problem constants ----------------
#define Ln   256
#define Cn   64
#define NUMn 64
#define Bn   32
#define NT   256
#define SA   68    // row stride (floats): 272B % 128 == 16 -> conflict-free LDS.128 phases
#define SV   260   // row stride (floats) for transposed K/V: 1040B % 128 == 16
#define SP   132   // row stride (floats) for P/Q region: 528B % 128 == 16

#define SZ (33554432ULL)  // B*NUM*L*C per tensor

// raw per-head projections of (x + emb) for all (b,t): [k|q|v][b][t][l][c]
__device__ float g_raw[3ULL * SZ];
// pre-transposed FFN weights: fk1,fk2,fq1,fq2,fx1,fx2 as [c][d]
__device__ float g_WT[6 * 4096];

// ---------------- shared memory layout (floats) ----------------
// OFF_A (17408 fl): Kt[64][SV] -> Vt[64][SV] -> {z,h,W1t,W2t}[64][SA] each
#define OFF_A  0
#define OFF_Z  (OFF_A)
#define OFF_H  (OFF_A + 64*SA)
#define OFF_W1 (OFF_A + 128*SA)
#define OFF_W2 (OFF_A + 192*SA)
#define OFF_P  (OFF_A + 256*SA)   // 64*SP = 8448 fl: Q staging [RB][SP] -> P 128-col chunk
#define OFF_C  (OFF_P + 64*SP)
#define C_G0   (OFF_C + 0)
#define C_B0   (OFF_C + 64)
#define C_G1   (OFF_C + 128)
#define C_B1   (OFF_C + 192)
#define C_F1B  (OFF_C + 256)
#define C_F2B  (OFF_C + 320)
#define SMEM_FLOATS (OFF_C + 384)
#define SMEM_BYTES  (SMEM_FLOATS * 4)   // 104,960 B -> 2 CTAs/SM

typedef unsigned long long u64t;

__device__ __forceinline__ u64t fma2(u64t a, u64t b, u64t c) {
  u64t d; asm("fma.rn.f32x2 %0, %1, %2, %3;" : "=l"(d) : "l"(a), "l"(b), "l"(c)); return d;
}
__device__ __forceinline__ u64t pack2(float x, float y) {
  u64t d; asm("mov.b64 %0, {%1, %2};" : "=l"(d) : "f"(x), "f"(y)); return d;
}
__device__ __forceinline__ float2 unpack2(u64t v) {
  float2 r; asm("mov.b64 {%0, %1}, %2;" : "=f"(r.x), "=f"(r.y) : "l"(v)); return r;
}
__device__ __forceinline__ float f4c(const float4& v, int k) {
  return (k == 0) ? v.x : (k == 1) ? v.y : (k == 2) ? v.z : v.w;
}

struct AttnParams {
  const float *g0x, *b0x, *g1x, *b1x;
  const float *g0k, *b0k, *g1k, *b1k;
  const float *g0q, *b0q, *g1q, *b1q;
  const float *fx1b, *fx2b, *fk1b, *fk2b, *fq1b, *fq2b;
  float *K, *Q, *V;
  int t;
};

__device__ __forceinline__ float hmax16(float v) {
  v = fmaxf(v, __shfl_xor_sync(0xffffffffu, v, 1));
  v = fmaxf(v, __shfl_xor_sync(0xffffffffu, v, 2));
  v = fmaxf(v, __shfl_xor_sync(0xffffffffu, v, 4));
  v = fmaxf(v, __shfl_xor_sync(0xffffffffu, v, 8));
  return v;
}
__device__ __forceinline__ float hsum16(float v) {
  v += __shfl_xor_sync(0xffffffffu, v, 1);
  v += __shfl_xor_sync(0xffffffffu, v, 2);
  v += __shfl_xor_sync(0xffffffffu, v, 4);
  v += __shfl_xor_sync(0xffffffffu, v, 8);
  return v;
}

// gather-transpose: src [256][64] row-major gmem -> dst [64][SV] smem (c-major)
__device__ __forceinline__ void load_transposed_LxC(float* dst, const float* __restrict__ src, int tid) {
  #pragma unroll
  for (int it = 0; it < 16; it++) {
    int i = tid + it * NT;          // 0..4095
    int c  = i & 63;
    int n4 = (i >> 6) << 2;
    float v0 = __ldg(src + (n4 + 0) * 64 + c);
    float v1 = __ldg(src + (n4 + 1) * 64 + c);
    float v2 = __ldg(src + (n4 + 2) * 64 + c);
    float v3 = __ldg(src + (n4 + 3) * 64 + c);
    *(float4*)(dst + c * SV + n4) = make_float4(v0, v1, v2, v3);
  }
}

// coalesced row-copy: gmem [64][64] (already transposed) -> smem [64][SA]
__device__ __forceinline__ void load_cmajor_64x64(float* dst, const float* __restrict__ src, int tid) {
  const float4* s4 = (const float4*)src;
  #pragma unroll
  for (int it = 0; it < 4; it++) {
    int i = tid + it * NT;          // 0..1023
    int r = i >> 4, c4 = (i & 15) << 2;
    *(float4*)(dst + r * SA + c4) = __ldg(s4 + i);
  }
}

// ============ one-time: transpose the 6 FFN weight matrices into g_WT ============
__global__ __launch_bounds__(NT)
void transpose_w_kernel(const float* s0, const float* s1, const float* s2,
                        const float* s3, const float* s4, const float* s5) {
  __shared__ float tile[64][65];
  const float* srcs[6] = {s0, s1, s2, s3, s4, s5};
  const float* src = srcs[blockIdx.x];
  float* dst = g_WT + blockIdx.x * 4096;
  const int tid = threadIdx.x;
  for (int i = tid; i < 4096; i += NT) tile[i >> 6][i & 63] = __ldg(src + i);
  __syncthreads();
  for (int i = tid; i < 4096; i += NT) dst[i] = tile[i & 63][i >> 6];
}

// ============ precompute: raw = proj(x + emb) for every (b,t); also K/Q/V at t=0 ============
__global__ __launch_bounds__(NT)
void precompute_raw_kernel(const float* __restrict__ x, const float* __restrict__ emb,
                           const float* __restrict__ Wk, const float* __restrict__ bk,
                           const float* __restrict__ Wq, const float* __restrict__ bq,
                           const float* __restrict__ Wv, const float* __restrict__ bv,
                           float* __restrict__ K, float* __restrict__ Q, float* __restrict__ V) {
  __shared__ float w[3 * 512 + 3 * 64];
  const int tid = threadIdx.x;
  for (int i = tid; i < 512; i += NT) {
    w[i]        = __ldg(Wk + i);
    w[512 + i]  = __ldg(Wq + i);
    w[1024 + i] = __ldg(Wv + i);
  }
  if (tid < 64) {
    w[1536 + tid] = __ldg(bk + tid);
    w[1600 + tid] = __ldg(bq + tid);
    w[1664 + tid] = __ldg(bv + tid);
  }
  __syncthreads();

  const size_t task = (size_t)blockIdx.x * NT + tid;
  const int h = (int)(task & 7);
  const size_t row = task >> 3;
  const int l = (int)(row & 255);
  const int t = (int)((row >> 8) & 63);

  float xe[8];
  const float* xr = x + row * 64 + h * 8;
  const float* er = emb + l * 64 + h * 8;
  #pragma unroll
  for (int d = 0; d < 8; d++) xe[d] = __ldg(xr + d) + __ldg(er + d);

  float* outs0[3] = {K, Q, V};
  #pragma unroll
  for (int pidx = 0; pidx < 3; pidx++) {
    const float* W  = w + pidx * 512 + h * 64;
    const float* bb = w + 1536 + pidx * 64 + h * 8;
    float acc[8];
    #pragma unroll
    for (int e = 0; e < 8; e++) acc[e] = bb[e];
    #pragma unroll
    for (int d = 0; d < 8; d++) {
      float xv = xe[d];
      #pragma unroll
      for (int e = 0; e < 8; e++) acc[e] = fmaf(xv, W[d * 8 + e], acc[e]);
    }
    float* dst = g_raw + (size_t)pidx * SZ + row * 64 + h * 8;
    #pragma unroll
    for (int e = 0; e < 8; e++) dst[e] = acc[e];
    if (t == 0) {
      float* d2 = outs0[pidx] + row * 64 + h * 8;
      #pragma unroll
      for (int e = 0; e < 8; e++) d2[e] = acc[e];
    }
  }
}

// ============ attention body (RPT rows per thread; RB = 16*RPT rows per CTA) ============
// mode 0: k-attn  keys=raw_k[t], vals=raw_k[t], queries=Q[t-1]   -> K[t]
// mode 1: q-attn  keys=K[t-1],   vals=raw_q[t], queries=raw_q[t] -> Q[t]
// mode 2: v-attn  keys=K[t],     vals=raw_v[t], queries=Q[t]     -> V[t]
template <int RPT>
__device__ __forceinline__ void attn_body(const AttnParams& p, int mode, int t, int rb, float* sm) {
  const int tid = threadIdx.x;
  const int b   = blockIdx.y;

  const size_t bOff    = (size_t)b * NUMn * Ln * Cn;
  const size_t curOff  = bOff + (size_t)t * Ln * Cn;
  const size_t prevOff = bOff + (size_t)(t - 1) * Ln * Cn;
  const float* rawK = g_raw;
  const float* rawQ = g_raw + SZ;
  const float* rawV = g_raw + 2 * SZ;

  const float *g0, *b0, *g1, *b1, *fb1, *fb2;
  const float *keysG, *qG, *valsG, *w1, *w2;
  float* outG;
  if (mode == 0) {
    g0 = p.g0k; b0 = p.b0k; g1 = p.g1k; b1 = p.b1k;
    fb1 = p.fk1b; fb2 = p.fk2b;
    w1 = g_WT + 0 * 4096; w2 = g_WT + 1 * 4096;
    keysG = rawK + curOff; valsG = rawK + curOff;
    qG = p.Q + prevOff + (size_t)rb * Cn;
    outG = p.K + curOff;
  } else if (mode == 1) {
    g0 = p.g0q; b0 = p.b0q; g1 = p.g1q; b1 = p.b1q;
    fb1 = p.fq1b; fb2 = p.fq2b;
    w1 = g_WT + 2 * 4096; w2 = g_WT + 3 * 4096;
    keysG = p.K + prevOff; valsG = rawQ + curOff;
    qG = rawQ + curOff + (size_t)rb * Cn;
    outG = p.Q + curOff;
  } else {
    g0 = p.g0x; b0 = p.b0x; g1 = p.g1x; b1 = p.b1x;
    fb1 = p.fx1b; fb2 = p.fx2b;
    w1 = g_WT + 4 * 4096; w2 = g_WT + 5 * 4096;
    keysG = p.K + curOff; valsG = rawV + curOff;
    qG = p.Q + curOff + (size_t)rb * Cn;
    outG = p.V + curOff;
  }

  // ---- load Kt (gather transpose), Q rows (stride SP), consts ----
  load_transposed_LxC(sm + OFF_A, keysG, tid);
  {
    const float4* q4 = (const float4*)qG;
    #pragma unroll
    for (int it = 0; it < RPT; it++) {
      int i = tid + it * NT;
      float4 v = __ldg(q4 + i);
      int l = i >> 4, c = (i & 15) << 2;
      *(float4*)(sm + OFF_P + l * SP + c) = v;
    }
    if (tid < 64) {
      sm[C_G0  + tid] = __ldg(g0 + tid);
      sm[C_B0  + tid] = __ldg(b0 + tid);
      sm[C_G1  + tid] = __ldg(g1 + tid);
      sm[C_B1  + tid] = __ldg(b1 + tid);
      sm[C_F1B + tid] = __ldg(fb1 + tid);
      sm[C_F2B + tid] = __ldg(fb2 + tid);
    }
  }
  __syncthreads();

  const int rg = tid >> 4;   // 16 row-groups, RPT rows each
  const int cg = tid & 15;   // thread owns S cols 4*cg + 64*q + e  (q=0..3, e=0..3)

  // ---- S = Q @ Kt (RB x 256, k=64), packed f32x2 along n ----
  u64t acc[RPT][4][2];
  #pragma unroll
  for (int i = 0; i < RPT; i++)
    #pragma unroll
    for (int q = 0; q < 4; q++) { acc[i][q][0] = 0ull; acc[i][q][1] = 0ull; }
  {
    const float* qb = sm + OFF_P + (rg * RPT) * SP;
    #pragma unroll 4
    for (int d4 = 0; d4 < 64; d4 += 4) {
      float4 qv[RPT];
      #pragma unroll
      for (int i = 0; i < RPT; i++) qv[i] = *(const float4*)(qb + i * SP + d4);
      #pragma unroll
      for (int dd = 0; dd < 4; dd++) {
        u64t qp[RPT];
        #pragma unroll
        for (int i = 0; i < RPT; i++) { float s = f4c(qv[i], dd); qp[i] = pack2(s, s); }
        const float* kt = sm + OFF_A + (d4 + dd) * SV + 4 * cg;
        #pragma unroll
        for (int q = 0; q < 4; q++) {
          ulonglong2 kv = *(const ulonglong2*)(kt + 64 * q);
          #pragma unroll
          for (int i = 0; i < RPT; i++) {
            acc[i][q][0] = fma2(qp[i], kv.x, acc[i][q][0]);
            acc[i][q][1] = fma2(qp[i], kv.y, acc[i][q][1]);
          }
        }
      }
    }
  }
  __syncthreads();  // Kt + Q reads done; A region free

  // ---- load Vt into A (gather transpose; LDG latency overlaps softmax) ----
  load_transposed_LxC(sm + OFF_A, valsG, tid);

  // ---- softmax in registers, fold /sqrt(64) ----
  float pv[RPT][16];
  #pragma unroll
  for (int i = 0; i < RPT; i++) {
    #pragma unroll
    for (int q = 0; q < 4; q++) {
      float2 e0 = unpack2(acc[i][q][0]);
      float2 e1 = unpack2(acc[i][q][1]);
      pv[i][q * 4 + 0] = e0.x; pv[i][q * 4 + 1] = e0.y;
      pv[i][q * 4 + 2] = e1.x; pv[i][q * 4 + 3] = e1.y;
    }
    float m = pv[i][0];
    #pragma unroll
    for (int j = 1; j < 16; j++) m = fmaxf(m, pv[i][j]);
    m = hmax16(m);
    float s = 0.f;
    #pragma unroll
    for (int j = 0; j < 16; j++) {
      float e = __expf(pv[i][j] - m);
      pv[i][j] = e;
      s += e;
    }
    s = hsum16(s);
    float sc = 0.125f / s;
    #pragma unroll
    for (int j = 0; j < 16; j++) pv[i][j] *= sc;
  }

  // ---- O = P @ V, k in 2 chunks of 128 via smem P tile (dead Q region) ----
  u64t acc2[RPT][4];
  #pragma unroll
  for (int i = 0; i < RPT; i++)
    #pragma unroll
    for (int c2 = 0; c2 < 4; c2++) acc2[i][c2] = 0ull;
  #pragma unroll
  for (int ch = 0; ch < 2; ch++) {
    __syncthreads();  // ch0: Vt stores + Q reads complete; ch1: chunk-0 reads complete
    #pragma unroll
    for (int i = 0; i < RPT; i++) {
      float* pr = sm + OFF_P + (rg * RPT + i) * SP;
      *(float4*)(pr + 4 * cg) =
          make_float4(pv[i][(2*ch)*4 + 0], pv[i][(2*ch)*4 + 1], pv[i][(2*ch)*4 + 2], pv[i][(2*ch)*4 + 3]);
      *(float4*)(pr + 64 + 4 * cg) =
          make_float4(pv[i][(2*ch+1)*4 + 0], pv[i][(2*ch+1)*4 + 1], pv[i][(2*ch+1)*4 + 2], pv[i][(2*ch+1)*4 + 3]);
    }
    __syncthreads();  // chunk visible
    const float* pb = sm + OFF_P + (rg * RPT) * SP;
    const float* vb = sm + OFF_A + cg * SV + ch * 128;
    #pragma unroll 4
    for (int m4 = 0; m4 < 128; m4 += 4) {
      ulonglong2 pp[RPT];
      #pragma unroll
      for (int i = 0; i < RPT; i++) pp[i] = *(const ulonglong2*)(pb + i * SP + m4);
      #pragma unroll
      for (int c2 = 0; c2 < 4; c2++) {
        ulonglong2 vv = *(const ulonglong2*)(vb + c2 * (16 * SV) + m4);
        #pragma unroll
        for (int i = 0; i < RPT; i++) {
          acc2[i][c2] = fma2(pp[i].x, vv.x, acc2[i][c2]);
          acc2[i][c2] = fma2(pp[i].y, vv.y, acc2[i][c2]);
        }
      }
    }
  }

  // ---- residual (+v at query row) + LayerNorm 1 ----
  float z[RPT][4];
  {
    float sum[RPT], sq[RPT];
    #pragma unroll
    for (int i = 0; i < RPT; i++) { sum[i] = 0.f; sq[i] = 0.f; }
    #pragma unroll
    for (int i = 0; i < RPT; i++) {
      int n = rb + rg * RPT + i;
      #pragma unroll
      for (int c2 = 0; c2 < 4; c2++) {
        float2 tacc = unpack2(acc2[i][c2]);
        float o = tacc.x + tacc.y + sm[OFF_A + (cg + 16 * c2) * SV + n];
        z[i][c2] = o;
        sum[i] += o;
        sq[i]  += o * o;
      }
    }
    #pragma unroll
    for (int i = 0; i < RPT; i++) { sum[i] = hsum16(sum[i]); sq[i] = hsum16(sq[i]); }
    #pragma unroll
    for (int i = 0; i < RPT; i++) {
      float mean = sum[i] * (1.f / 64.f);
      float var  = sq[i] * (1.f / 64.f) - mean * mean;
      float rs = rsqrtf(var + 1e-5f);
      #pragma unroll
      for (int c2 = 0; c2 < 4; c2++) {
        int c = cg + 16 * c2;
        z[i][c2] = (z[i][c2] - mean) * rs * sm[C_G0 + c] + sm[C_B0 + c];
      }
    }
  }
  __syncthreads();  // Vt + P dead; A region free

  // ---- stage z; load W1t,W2t (pre-transposed, coalesced) ----
  #pragma unroll
  for (int i = 0; i < RPT; i++)
    #pragma unroll
    for (int c2 = 0; c2 < 4; c2++)
      sm[OFF_Z + (rg * RPT + i) * SA + cg + 16 * c2] = z[i][c2];
  load_cmajor_64x64(sm + OFF_W1, w1, tid);
  load_cmajor_64x64(sm + OFF_W2, w2, tid);
  __syncthreads();

  // ---- FFN layer 1: h = relu(z @ W1 + b1), packed f32x2 along k ----
  {
    u64t hacc[RPT][4];
    #pragma unroll
    for (int i = 0; i < RPT; i++)
      #pragma unroll
      for (int c2 = 0; c2 < 4; c2++) hacc[i][c2] = 0ull;
    const float* zb = sm + OFF_Z + (rg * RPT) * SA;
    const float* wb = sm + OFF_W1 + cg * SA;
    #pragma unroll 4
    for (int d4 = 0; d4 < 64; d4 += 4) {
      ulonglong2 zz[RPT];
      #pragma unroll
      for (int i = 0; i < RPT; i++) zz[i] = *(const ulonglong2*)(zb + i * SA + d4);
      #pragma unroll
      for (int c2 = 0; c2 < 4; c2++) {
        ulonglong2 ww = *(const ulonglong2*)(wb + c2 * (16 * SA) + d4);
        #pragma unroll
        for (int i = 0; i < RPT; i++) {
          hacc[i][c2] = fma2(zz[i].x, ww.x, hacc[i][c2]);
          hacc[i][c2] = fma2(zz[i].y, ww.y, hacc[i][c2]);
        }
      }
    }
    #pragma unroll
    for (int i = 0; i < RPT; i++)
      #pragma unroll
      for (int c2 = 0; c2 < 4; c2++) {
        float2 th = unpack2(hacc[i][c2]);
        float hv = th.x + th.y + sm[C_F1B + cg + 16 * c2];
        sm[OFF_H + (rg * RPT + i) * SA + cg + 16 * c2] = fmaxf(hv, 0.f);
      }
  }
  __syncthreads();

  // ---- FFN layer 2 + residual + LayerNorm 2 + store ----
  {
    u64t facc[RPT][4];
    #pragma unroll
    for (int i = 0; i < RPT; i++)
      #pragma unroll
      for (int c2 = 0; c2 < 4; c2++) facc[i][c2] = 0ull;
    const float* hb = sm + OFF_H + (rg * RPT) * SA;
    const float* wb = sm + OFF_W2 + cg * SA;
    #pragma unroll 4
    for (int d4 = 0; d4 < 64; d4 += 4) {
      ulonglong2 hh[RPT];
      #pragma unroll
      for (int i = 0; i < RPT; i++) hh[i] = *(const ulonglong2*)(hb + i * SA + d4);
      #pragma unroll
      for (int c2 = 0; c2 < 4; c2++) {
        ulonglong2 ww = *(const ulonglong2*)(wb + c2 * (16 * SA) + d4);
        #pragma unroll
        for (int i = 0; i < RPT; i++) {
          facc[i][c2] = fma2(hh[i].x, ww.x, facc[i][c2]);
          facc[i][c2] = fma2(hh[i].y, ww.y, facc[i][c2]);
        }
      }
    }
    float f[RPT][4];
    float sum[RPT], sq[RPT];
    #pragma unroll
    for (int i = 0; i < RPT; i++) { sum[i] = 0.f; sq[i] = 0.f; }
    #pragma unroll
    for (int i = 0; i < RPT; i++)
      #pragma unroll
      for (int c2 = 0; c2 < 4; c2++) {
        float2 tf = unpack2(facc[i][c2]);
        float o = tf.x + tf.y + sm[C_F2B + cg + 16 * c2] + z[i][c2];
        f[i][c2] = o;
        sum[i] += o;
        sq[i]  += o * o;
      }
    #pragma unroll
    for (int i = 0; i < RPT; i++) { sum[i] = hsum16(sum[i]); sq[i] = hsum16(sq[i]); }
    #pragma unroll
    for (int i = 0; i < RPT; i++) {
      float mean = sum[i] * (1.f / 64.f);
      float var  = sq[i] * (1.f / 64.f) - mean * mean;
      float rs = rsqrtf(var + 1e-5f);
      float* orow = outG + (size_t)(rb + rg * RPT + i) * Cn;
      #pragma unroll
      for (int c2 = 0; c2 < 4; c2++) {
        int c = cg + 16 * c2;
        orow[c] = (f[i][c2] - mean) * rs * sm[C_G1 + c] + sm[C_B1 + c];
      }
    }
  }
}

// job 0: A(t)            grid (8,32):  bx>>2 -> mode 0/1 at t, rb=(bx&3)*64
// job 1: B(t) + A(t+1)   grid (12,32): bx<8 -> A(t+1); bx 8..11 -> B(t) rb=(bx-8)*64
// job 2: B(t)            grid (4,32):  mode 2 at t, rb=bx*64
__global__ __launch_bounds__(NT, 2)
void attn_step_kernel(AttnParams p, int job) {
  extern __shared__ float sm[];
  const int bx = (int)blockIdx.x;
  if (job == 1) {
    if (bx < 8) attn_body<4>(p, bx >> 2, p.t + 1, (bx & 3) * 64, sm);
    else        attn_body<4>(p, 2, p.t, (bx - 8) * 64, sm);
  } else if (job == 0) {
    attn_body<4>(p, bx >> 2, p.t, (bx & 3) * 64, sm);
  } else {
    attn_body<4>(p, 2, p.t, bx * 64, sm);
  }
}

extern "C" void kernel_launch(void* const* d_in, const int* in_sizes, int n_in,
                              void* d_out, int out_size) {
  (void)in_sizes; (void)n_in; (void)out_size;
  const float* x   = (const float*)d_in[0];
  const float* emb = (const float*)d_in[1];
  const float* Wk  = (const float*)d_in[2];
  const float* bk  = (const float*)d_in[3];
  const float* Wq  = (const float*)d_in[4];
  const float* bq  = (const float*)d_in[5];
  const float* Wv  = (const float*)d_in[6];
  const float* bv  = (const float*)d_in[7];

  AttnParams p;
  p.g0x  = (const float*)d_in[8];   p.b0x = (const float*)d_in[9];
  p.g1x  = (const float*)d_in[10];  p.b1x = (const float*)d_in[11];
  p.g0k  = (const float*)d_in[12];  p.b0k = (const float*)d_in[13];
  p.g1k  = (const float*)d_in[14];  p.b1k = (const float*)d_in[15];
  p.g0q  = (const float*)d_in[16];  p.b0q = (const float*)d_in[17];
  p.g1q  = (const float*)d_in[18];  p.b1q = (const float*)d_in[19];
  const float* fx1w = (const float*)d_in[20];  p.fx1b = (const float*)d_in[21];
  const float* fx2w = (const float*)d_in[22];  p.fx2b = (const float*)d_in[23];
  const float* fk1w = (const float*)d_in[24];  p.fk1b = (const float*)d_in[25];
  const float* fk2w = (const float*)d_in[26];  p.fk2b = (const float*)d_in[27];
  const float* fq1w = (const float*)d_in[28];  p.fq1b = (const float*)d_in[29];
  const float* fq2w = (const float*)d_in[30];  p.fq2b = (const float*)d_in[31];

  float* out = (float*)d_out;
  p.K = out;
  p.Q = out + SZ;
  p.V = out + 2 * SZ;

  cudaFuncSetAttribute((const void*)attn_step_kernel,
                       cudaFuncAttributeMaxDynamicSharedMemorySize, SMEM_BYTES);

  // one-time prep: transposed FFN weights + raw projections (and K/Q/V at t=0)
  transpose_w_kernel<<<6, NT>>>(fk1w, fk2w, fq1w, fq2w, fx1w, fx2w);
  precompute_raw_kernel<<<(Bn * NUMn * Ln * 8) / NT, NT>>>(x, emb, Wk, bk, Wq, bq, Wv, bv,
                                                           p.K, p.Q, p.V);

  // A(1)
  p.t = 1;
  attn_step_kernel<<<dim3(8, Bn), NT, SMEM_BYTES>>>(p, 0);
  // merged B(t) + A(t+1), t = 1..62  (384 CTAs, no idle blocks)
  for (int t = 1; t <= 62; t++) {
    p.t = t;
    attn_step_kernel<<<dim3(12, Bn), NT, SMEM_BYTES>>>(p, 1);
  }
  // B(63)
  p.t = 63;
  attn_step_kernel<<<dim3(4, Bn), NT, SMEM_BYTES>>>(p, 2);
}

// round 15
// speedup vs baseline: 1.2812x; 1.0209x over previous
#include <cuda_runtime.h>

// ---------------- problem constants ----------------
#define Ln   256
#define Cn   64
#define NUMn 64
#define Bn   32
#define NT   256
#define SA   68    // row stride (floats): 272B % 128 == 16 -> conflict-free LDS.128 phases
#define SV   260   // row stride (floats) for c-major K/V tiles: 1040B % 128 == 16
#define SP   132   // row stride (floats) for P/Q region: 528B % 128 == 16
#define ST   68    // row stride for output-transpose staging tile (mult of 4 -> aligned LDS.128)

#define SZ (33554432ULL)  // B*NUM*L*C per tensor

// gmem scratch (device globals = sanctioned scratch)
__device__ float g_rawQ[SZ];     // raw q projections, row-major [b][t][l][c]
__device__ float g_rawKT[SZ];    // raw k, c-major [b][t][c][l]
__device__ float g_rawQT[SZ];    // raw q, c-major
__device__ float g_rawVT[SZ];    // raw v, c-major
__device__ float g_KT[SZ];       // shadow of output K, c-major
__device__ float g_WT[6 * 4096]; // fk1,fk2,fq1,fq2,fx1,fx2 transposed [c][d]

// ---------------- shared memory layout (floats) ----------------
// OFF_A (17408 fl): Kt[64][SV] -> Vt[64][SV] -> {z,h,W1t,W2t}[64][SA] each
#define OFF_A  0
#define OFF_Z  (OFF_A)
#define OFF_H  (OFF_A + 64*SA)
#define OFF_W1 (OFF_A + 128*SA)
#define OFF_W2 (OFF_A + 192*SA)
#define OFF_P  (OFF_A + 256*SA)   // 64*SP = 8448 fl: Q staging -> P chunk -> out-transpose stage
#define OFF_C  (OFF_P + 64*SP)
#define C_G0   (OFF_C + 0)
#define C_B0   (OFF_C + 64)
#define C_G1   (OFF_C + 128)
#define C_B1   (OFF_C + 192)
#define C_F1B  (OFF_C + 256)
#define C_F2B  (OFF_C + 320)
#define SMEM_FLOATS (OFF_C + 384)
#define SMEM_BYTES  (SMEM_FLOATS * 4)   // 104,960 B -> 2 CTAs/SM

typedef unsigned long long u64t;

__device__ __forceinline__ u64t fma2(u64t a, u64t b, u64t c) {
  u64t d; asm("fma.rn.f32x2 %0, %1, %2, %3;" : "=l"(d) : "l"(a), "l"(b), "l"(c)); return d;
}
__device__ __forceinline__ u64t pack2(float x, float y) {
  u64t d; asm("mov.b64 %0, {%1, %2};" : "=l"(d) : "f"(x), "f"(y)); return d;
}
__device__ __forceinline__ float2 unpack2(u64t v) {
  float2 r; asm("mov.b64 {%0, %1}, %2;" : "=f"(r.x), "=f"(r.y) : "l"(v)); return r;
}
__device__ __forceinline__ float f4c(const float4& v, int k) {
  return (k == 0) ? v.x : (k == 1) ? v.y : (k == 2) ? v.z : v.w;
}

struct AttnParams {
  const float *g0x, *b0x, *g1x, *b1x;
  const float *g0k, *b0k, *g1k, *b1k;
  const float *g0q, *b0q, *g1q, *b1q;
  const float *fx1b, *fx2b, *fk1b, *fk2b, *fq1b, *fq2b;
  float *K, *Q, *V;
  int t;
};

__device__ __forceinline__ float hmax16(float v) {
  v = fmaxf(v, __shfl_xor_sync(0xffffffffu, v, 1));
  v = fmaxf(v, __shfl_xor_sync(0xffffffffu, v, 2));
  v = fmaxf(v, __shfl_xor_sync(0xffffffffu, v, 4));
  v = fmaxf(v, __shfl_xor_sync(0xffffffffu, v, 8));
  return v;
}
__device__ __forceinline__ float hsum16(float v) {
  v += __shfl_xor_sync(0xffffffffu, v, 1);
  v += __shfl_xor_sync(0xffffffffu, v, 2);
  v += __shfl_xor_sync(0xffffffffu, v, 4);
  v += __shfl_xor_sync(0xffffffffu, v, 8);
  return v;
}

// coalesced row-copy: gmem [64][256] (c-major) -> smem [64][SV]
__device__ __forceinline__ void load_cmajor_64x256(float* dst, const float* __restrict__ src, int tid) {
  const float4* s4 = (const float4*)src;
  #pragma unroll
  for (int it = 0; it < 16; it++) {
    int i = tid + it * NT;          // 0..4095
    int r = i >> 6, c4 = (i & 63) << 2;
    *(float4*)(dst + r * SV + c4) = __ldg(s4 + i);
  }
}

// coalesced row-copy: gmem [64][64] (already transposed) -> smem [64][SA]
__device__ __forceinline__ void load_cmajor_64x64(float* dst, const float* __restrict__ src, int tid) {
  const float4* s4 = (const float4*)src;
  #pragma unroll
  for (int it = 0; it < 4; it++) {
    int i = tid + it * NT;          // 0..1023
    int r = i >> 4, c4 = (i & 15) << 2;
    *(float4*)(dst + r * SA + c4) = __ldg(s4 + i);
  }
}

// ============ one-time: transpose the 6 FFN weight matrices into g_WT ============
__global__ __launch_bounds__(NT)
void transpose_w_kernel(const float* s0, const float* s1, const float* s2,
                        const float* s3, const float* s4, const float* s5) {
  __shared__ float tile[64][65];
  const float* srcs[6] = {s0, s1, s2, s3, s4, s5};
  const float* src = srcs[blockIdx.x];
  float* dst = g_WT + blockIdx.x * 4096;
  const int tid = threadIdx.x;
  for (int i = tid; i < 4096; i += NT) tile[i >> 6][i & 63] = __ldg(src + i);
  __syncthreads();
  for (int i = tid; i < 4096; i += NT) dst[i] = tile[i & 63][i >> 6];
}

// ============ precompute: raw projections (+transposed variants); K/Q/V & KT at t=0 ============
// grid = Bn*NUMn*8; block covers one (b,t) 32-row slab (l0..l0+31) x 8 heads
__global__ __launch_bounds__(NT)
void precompute_raw_kernel(const float* __restrict__ x, const float* __restrict__ emb,
                           const float* __restrict__ Wk, const float* __restrict__ bk,
                           const float* __restrict__ Wq, const float* __restrict__ bq,
                           const float* __restrict__ Wv, const float* __restrict__ bv,
                           float* __restrict__ K, float* __restrict__ Q, float* __restrict__ V) {
  __shared__ float w[3 * 512 + 3 * 64];
  __shared__ float tr[3][64][33];
  const int tid = threadIdx.x;
  for (int i = tid; i < 512; i += NT) {
    w[i]        = __ldg(Wk + i);
    w[512 + i]  = __ldg(Wq + i);
    w[1024 + i] = __ldg(Wv + i);
  }
  if (tid < 64) {
    w[1536 + tid] = __ldg(bk + tid);
    w[1600 + tid] = __ldg(bq + tid);
    w[1664 + tid] = __ldg(bv + tid);
  }
  __syncthreads();

  const int bidx  = blockIdx.x;
  const int btIdx = bidx >> 3;          // b*64 + t
  const int l0    = (bidx & 7) << 5;
  const int t     = btIdx & 63;
  const int h  = tid & 7;
  const int dl = tid >> 3;              // 0..31
  const int l  = l0 + dl;
  const size_t row = (size_t)btIdx * 256 + l;

  float xe[8];
  const float* xr = x + row * 64 + h * 8;
  const float* er = emb + l * 64 + h * 8;
  #pragma unroll
  for (int d = 0; d < 8; d++) xe[d] = __ldg(xr + d) + __ldg(er + d);

  float* outs0[3] = {K, Q, V};
  #pragma unroll
  for (int pidx = 0; pidx < 3; pidx++) {
    const float* W  = w + pidx * 512 + h * 64;
    const float* bb = w + 1536 + pidx * 64 + h * 8;
    float acc[8];
    #pragma unroll
    for (int e = 0; e < 8; e++) acc[e] = bb[e];
    #pragma unroll
    for (int d = 0; d < 8; d++) {
      float xv = xe[d];
      #pragma unroll
      for (int e = 0; e < 8; e++) acc[e] = fmaf(xv, W[d * 8 + e], acc[e]);
    }
    #pragma unroll
    for (int e = 0; e < 8; e++) tr[pidx][h * 8 + e][dl] = acc[e];
    if (pidx == 1) {
      float* dq = g_rawQ + row * 64 + h * 8;
      #pragma unroll
      for (int e = 0; e < 8; e++) dq[e] = acc[e];
    }
    if (t == 0) {
      float* d2 = outs0[pidx] + row * 64 + h * 8;
      #pragma unroll
      for (int e = 0; e < 8; e++) d2[e] = acc[e];
    }
  }
  __syncthreads();

  // coalesced transposed writes: [c][l] slab
  const size_t base = (size_t)btIdx * 16384;
  for (int j = tid; j < 2048; j += NT) {
    int c = j >> 5, d = j & 31;
    size_t off = base + (size_t)c * 256 + l0 + d;
    g_rawKT[off] = tr[0][c][d];
    g_rawQT[off] = tr[1][c][d];
    g_rawVT[off] = tr[2][c][d];
    if (t == 0) g_KT[off] = tr[0][c][d];
  }
}

// ============ attention body (RPT=4 rows/thread; RB=64 rows per CTA) ============
// mode 0: k-attn  keysT=rawKT[t], vals=keys tile, queries=Q[t-1]  -> K[t] (+KT shadow, staged)
// mode 1: q-attn  keysT=KT[t-1],  valsT=rawQT[t], queries=rawQ[t] -> Q[t]
// mode 2: v-attn  keysT=KT[t],    valsT=rawVT[t], queries=Q[t]    -> V[t]
template <int RPT>
__device__ __forceinline__ void attn_body(const AttnParams& p, int mode, int t, int rb, float* sm) {
  const int tid = threadIdx.x;
  const int b   = blockIdx.y;

  const size_t bOff    = (size_t)b * NUMn * Ln * Cn;
  const size_t curOff  = bOff + (size_t)t * Ln * Cn;
  const size_t prevOff = bOff + (size_t)(t - 1) * Ln * Cn;

  const float *g0, *b0, *g1, *b1, *fb1, *fb2;
  const float *keysT, *qG, *valsT, *w1, *w2;
  float* outG;
  if (mode == 0) {
    g0 = p.g0k; b0 = p.b0k; g1 = p.g1k; b1 = p.b1k;
    fb1 = p.fk1b; fb2 = p.fk2b;
    w1 = g_WT + 0 * 4096; w2 = g_WT + 1 * 4096;
    keysT = g_rawKT + curOff; valsT = 0;   // vals == keys tile
    qG = p.Q + prevOff + (size_t)rb * Cn;
    outG = p.K + curOff;
  } else if (mode == 1) {
    g0 = p.g0q; b0 = p.b0q; g1 = p.g1q; b1 = p.b1q;
    fb1 = p.fq1b; fb2 = p.fq2b;
    w1 = g_WT + 2 * 4096; w2 = g_WT + 3 * 4096;
    keysT = g_KT + prevOff; valsT = g_rawQT + curOff;
    qG = g_rawQ + curOff + (size_t)rb * Cn;
    outG = p.Q + curOff;
  } else {
    g0 = p.g0x; b0 = p.b0x; g1 = p.g1x; b1 = p.b1x;
    fb1 = p.fx1b; fb2 = p.fx2b;
    w1 = g_WT + 4 * 4096; w2 = g_WT + 5 * 4096;
    keysT = g_KT + curOff; valsT = g_rawVT + curOff;
    qG = p.Q + curOff + (size_t)rb * Cn;
    outG = p.V + curOff;
  }

  // ---- load Kt (coalesced, pre-transposed), Q rows (stride SP), consts ----
  load_cmajor_64x256(sm + OFF_A, keysT, tid);
  {
    const float4* q4 = (const float4*)qG;
    #pragma unroll
    for (int it = 0; it < RPT; it++) {
      int i = tid + it * NT;
      float4 v = __ldg(q4 + i);
      int l = i >> 4, c = (i & 15) << 2;
      *(float4*)(sm + OFF_P + l * SP + c) = v;
    }
    if (tid < 64) {
      sm[C_G0  + tid] = __ldg(g0 + tid);
      sm[C_B0  + tid] = __ldg(b0 + tid);
      sm[C_G1  + tid] = __ldg(g1 + tid);
      sm[C_B1  + tid] = __ldg(b1 + tid);
      sm[C_F1B + tid] = __ldg(fb1 + tid);
      sm[C_F2B + tid] = __ldg(fb2 + tid);
    }
  }
  __syncthreads();

  const int rg = tid >> 4;   // 16 row-groups, RPT rows each
  const int cg = tid & 15;   // thread owns S cols 4*cg + 64*q + e  (q=0..3, e=0..3)

  // ---- S = Q @ Kt (RB x 256, k=64), packed f32x2 along n ----
  u64t acc[RPT][4][2];
  #pragma unroll
  for (int i = 0; i < RPT; i++)
    #pragma unroll
    for (int q = 0; q < 4; q++) { acc[i][q][0] = 0ull; acc[i][q][1] = 0ull; }
  {
    const float* qb = sm + OFF_P + (rg * RPT) * SP;
    #pragma unroll 4
    for (int d4 = 0; d4 < 64; d4 += 4) {
      float4 qv[RPT];
      #pragma unroll
      for (int i = 0; i < RPT; i++) qv[i] = *(const float4*)(qb + i * SP + d4);
      #pragma unroll
      for (int dd = 0; dd < 4; dd++) {
        u64t qp[RPT];
        #pragma unroll
        for (int i = 0; i < RPT; i++) { float s = f4c(qv[i], dd); qp[i] = pack2(s, s); }
        const float* kt = sm + OFF_A + (d4 + dd) * SV + 4 * cg;
        #pragma unroll
        for (int q = 0; q < 4; q++) {
          ulonglong2 kv = *(const ulonglong2*)(kt + 64 * q);
          #pragma unroll
          for (int i = 0; i < RPT; i++) {
            acc[i][q][0] = fma2(qp[i], kv.x, acc[i][q][0]);
            acc[i][q][1] = fma2(qp[i], kv.y, acc[i][q][1]);
          }
        }
      }
    }
  }
  __syncthreads();  // Kt + Q reads done; A region free

  // ---- load Vt into A (coalesced; skipped for mode 0 where vals == keys tile) ----
  if (mode != 0) load_cmajor_64x256(sm + OFF_A, valsT, tid);

  // ---- softmax in registers, fold /sqrt(64) ----
  float pv[RPT][16];
  #pragma unroll
  for (int i = 0; i < RPT; i++) {
    #pragma unroll
    for (int q = 0; q < 4; q++) {
      float2 e0 = unpack2(acc[i][q][0]);
      float2 e1 = unpack2(acc[i][q][1]);
      pv[i][q * 4 + 0] = e0.x; pv[i][q * 4 + 1] = e0.y;
      pv[i][q * 4 + 2] = e1.x; pv[i][q * 4 + 3] = e1.y;
    }
    float m = pv[i][0];
    #pragma unroll
    for (int j = 1; j < 16; j++) m = fmaxf(m, pv[i][j]);
    m = hmax16(m);
    float s = 0.f;
    #pragma unroll
    for (int j = 0; j < 16; j++) {
      float e = __expf(pv[i][j] - m);
      pv[i][j] = e;
      s += e;
    }
    s = hsum16(s);
    float sc = 0.125f / s;
    #pragma unroll
    for (int j = 0; j < 16; j++) pv[i][j] *= sc;
  }

  // ---- O = P @ V, k in 2 chunks of 128 via smem P tile (dead Q region) ----
  u64t acc2[RPT][4];
  #pragma unroll
  for (int i = 0; i < RPT; i++)
    #pragma unroll
    for (int c2 = 0; c2 < 4; c2++) acc2[i][c2] = 0ull;
  #pragma unroll
  for (int ch = 0; ch < 2; ch++) {
    __syncthreads();  // ch0: Vt stores + Q reads complete; ch1: chunk-0 reads complete
    #pragma unroll
    for (int i = 0; i < RPT; i++) {
      float* pr = sm + OFF_P + (rg * RPT + i) * SP;
      *(float4*)(pr + 4 * cg) =
          make_float4(pv[i][(2*ch)*4 + 0], pv[i][(2*ch)*4 + 1], pv[i][(2*ch)*4 + 2], pv[i][(2*ch)*4 + 3]);
      *(float4*)(pr + 64 + 4 * cg) =
          make_float4(pv[i][(2*ch+1)*4 + 0], pv[i][(2*ch+1)*4 + 1], pv[i][(2*ch+1)*4 + 2], pv[i][(2*ch+1)*4 + 3]);
    }
    __syncthreads();  // chunk visible
    const float* pb = sm + OFF_P + (rg * RPT) * SP;
    const float* vb = sm + OFF_A + cg * SV + ch * 128;
    #pragma unroll 4
    for (int m4 = 0; m4 < 128; m4 += 4) {
      ulonglong2 pp[RPT];
      #pragma unroll
      for (int i = 0; i < RPT; i++) pp[i] = *(const ulonglong2*)(pb + i * SP + m4);
      #pragma unroll
      for (int c2 = 0; c2 < 4; c2++) {
        ulonglong2 vv = *(const ulonglong2*)(vb + c2 * (16 * SV) + m4);
        #pragma unroll
        for (int i = 0; i < RPT; i++) {
          acc2[i][c2] = fma2(pp[i].x, vv.x, acc2[i][c2]);
          acc2[i][c2] = fma2(pp[i].y, vv.y, acc2[i][c2]);
        }
      }
    }
  }

  // ---- residual (+v at query row) + LayerNorm 1 ----
  float z[RPT][4];
  {
    float sum[RPT], sq[RPT];
    #pragma unroll
    for (int i = 0; i < RPT; i++) { sum[i] = 0.f; sq[i] = 0.f; }
    #pragma unroll
    for (int i = 0; i < RPT; i++) {
      int n = rb + rg * RPT + i;
      #pragma unroll
      for (int c2 = 0; c2 < 4; c2++) {
        float2 tacc = unpack2(acc2[i][c2]);
        float o = tacc.x + tacc.y + sm[OFF_A + (cg + 16 * c2) * SV + n];
        z[i][c2] = o;
        sum[i] += o;
        sq[i]  += o * o;
      }
    }
    #pragma unroll
    for (int i = 0; i < RPT; i++) { sum[i] = hsum16(sum[i]); sq[i] = hsum16(sq[i]); }
    #pragma unroll
    for (int i = 0; i < RPT; i++) {
      float mean = sum[i] * (1.f / 64.f);
      float var  = sq[i] * (1.f / 64.f) - mean * mean;
      float rs = rsqrtf(var + 1e-5f);
      #pragma unroll
      for (int c2 = 0; c2 < 4; c2++) {
        int c = cg + 16 * c2;
        z[i][c2] = (z[i][c2] - mean) * rs * sm[C_G0 + c] + sm[C_B0 + c];
      }
    }
  }
  __syncthreads();  // Vt + P dead; A region free

  // ---- stage z; load W1t,W2t (pre-transposed, coalesced) ----
  #pragma unroll
  for (int i = 0; i < RPT; i++)
    #pragma unroll
    for (int c2 = 0; c2 < 4; c2++)
      sm[OFF_Z + (rg * RPT + i) * SA + cg + 16 * c2] = z[i][c2];
  load_cmajor_64x64(sm + OFF_W1, w1, tid);
  load_cmajor_64x64(sm + OFF_W2, w2, tid);
  __syncthreads();

  // ---- FFN layer 1: h = relu(z @ W1 + b1), packed f32x2 along k ----
  {
    u64t hacc[RPT][4];
    #pragma unroll
    for (int i = 0; i < RPT; i++)
      #pragma unroll
      for (int c2 = 0; c2 < 4; c2++) hacc[i][c2] = 0ull;
    const float* zb = sm + OFF_Z + (rg * RPT) * SA;
    const float* wb = sm + OFF_W1 + cg * SA;
    #pragma unroll 4
    for (int d4 = 0; d4 < 64; d4 += 4) {
      ulonglong2 zz[RPT];
      #pragma unroll
      for (int i = 0; i < RPT; i++) zz[i] = *(const ulonglong2*)(zb + i * SA + d4);
      #pragma unroll
      for (int c2 = 0; c2 < 4; c2++) {
        ulonglong2 ww = *(const ulonglong2*)(wb + c2 * (16 * SA) + d4);
        #pragma unroll
        for (int i = 0; i < RPT; i++) {
          hacc[i][c2] = fma2(zz[i].x, ww.x, hacc[i][c2]);
          hacc[i][c2] = fma2(zz[i].y, ww.y, hacc[i][c2]);
        }
      }
    }
    #pragma unroll
    for (int i = 0; i < RPT; i++)
      #pragma unroll
      for (int c2 = 0; c2 < 4; c2++) {
        float2 th = unpack2(hacc[i][c2]);
        float hv = th.x + th.y + sm[C_F1B + cg + 16 * c2];
        sm[OFF_H + (rg * RPT + i) * SA + cg + 16 * c2] = fmaxf(hv, 0.f);
      }
  }
  __syncthreads();

  // ---- FFN layer 2 + residual + LayerNorm 2 + store (+staged KT shadow for mode 0) ----
  {
    u64t facc[RPT][4];
    #pragma unroll
    for (int i = 0; i < RPT; i++)
      #pragma unroll
      for (int c2 = 0; c2 < 4; c2++) facc[i][c2] = 0ull;
    const float* hb = sm + OFF_H + (rg * RPT) * SA;
    const float* wb = sm + OFF_W2 + cg * SA;
    #pragma unroll 4
    for (int d4 = 0; d4 < 64; d4 += 4) {
      ulonglong2 hh[RPT];
      #pragma unroll
      for (int i = 0; i < RPT; i++) hh[i] = *(const ulonglong2*)(hb + i * SA + d4);
      #pragma unroll
      for (int c2 = 0; c2 < 4; c2++) {
        ulonglong2 ww = *(const ulonglong2*)(wb + c2 * (16 * SA) + d4);
        #pragma unroll
        for (int i = 0; i < RPT; i++) {
          facc[i][c2] = fma2(hh[i].x, ww.x, facc[i][c2]);
          facc[i][c2] = fma2(hh[i].y, ww.y, facc[i][c2]);
        }
      }
    }
    float f[RPT][4];
    float sum[RPT], sq[RPT];
    #pragma unroll
    for (int i = 0; i < RPT; i++) { sum[i] = 0.f; sq[i] = 0.f; }
    #pragma unroll
    for (int i = 0; i < RPT; i++)
      #pragma unroll
      for (int c2 = 0; c2 < 4; c2++) {
        float2 tf = unpack2(facc[i][c2]);
        float o = tf.x + tf.y + sm[C_F2B + cg + 16 * c2] + z[i][c2];
        f[i][c2] = o;
        sum[i] += o;
        sq[i]  += o * o;
      }
    #pragma unroll
    for (int i = 0; i < RPT; i++) { sum[i] = hsum16(sum[i]); sq[i] = hsum16(sq[i]); }
    #pragma unroll
    for (int i = 0; i < RPT; i++) {
      float mean = sum[i] * (1.f / 64.f);
      float var  = sq[i] * (1.f / 64.f) - mean * mean;
      float rs = rsqrtf(var + 1e-5f);
      int n = rg * RPT + i;
      float* orow = outG + (size_t)(rb + n) * Cn;
      #pragma unroll
      for (int c2 = 0; c2 < 4; c2++) {
        int c = cg + 16 * c2;
        float val = (f[i][c2] - mean) * rs * sm[C_G1 + c] + sm[C_B1 + c];
        orow[c] = val;
        if (mode == 0) sm[OFF_P + c * ST + n] = val;  // stage transposed (OFF_P free)
      }
    }
  }

  // ---- mode 0 only: coalesced KT shadow from staged tile ----
  if (mode == 0) {
    __syncthreads();
    float* ktG = g_KT + curOff + rb;      // KT[c][rb + n], row stride 256
    #pragma unroll
    for (int it = 0; it < 4; it++) {
      int i = tid + it * NT;              // 0..1023
      int r = i >> 4, n4 = (i & 15) << 2;
      float4 v = *(const float4*)(sm + OFF_P + r * ST + n4);
      *(float4*)(ktG + (size_t)r * 256 + n4) = v;
    }
  }
}

// job 0: A(t)            grid (8,32):  bx>>2 -> mode 0/1 at t, rb=(bx&3)*64
// job 1: B(t) + A(t+1)   grid (12,32): bx<8 -> A(t+1); bx 8..11 -> B(t) rb=(bx-8)*64
// job 2: B(t)            grid (4,32):  mode 2 at t, rb=bx*64
__global__ __launch_bounds__(NT, 2)
void attn_step_kernel(AttnParams p, int job) {
  extern __shared__ float sm[];
  const int bx = (int)blockIdx.x;
  if (job == 1) {
    if (bx < 8) attn_body<4>(p, bx >> 2, p.t + 1, (bx & 3) * 64, sm);
    else        attn_body<4>(p, 2, p.t, (bx - 8) * 64, sm);
  } else if (job == 0) {
    attn_body<4>(p, bx >> 2, p.t, (bx & 3) * 64, sm);
  } else {
    attn_body<4>(p, 2, p.t, bx * 64, sm);
  }
}

extern "C" void kernel_launch(void* const* d_in, const int* in_sizes, int n_in,
                              void* d_out, int out_size) {
  (void)in_sizes; (void)n_in; (void)out_size;
  const float* x   = (const float*)d_in[0];
  const float* emb = (const float*)d_in[1];
  const float* Wk  = (const float*)d_in[2];
  const float* bk  = (const float*)d_in[3];
  const float* Wq  = (const float*)d_in[4];
  const float* bq  = (const float*)d_in[5];
  const float* Wv  = (const float*)d_in[6];
  const float* bv  = (const float*)d_in[7];

  AttnParams p;
  p.g0x  = (const float*)d_in[8];   p.b0x = (const float*)d_in[9];
  p.g1x  = (const float*)d_in[10];  p.b1x = (const float*)d_in[11];
  p.g0k  = (const float*)d_in[12];  p.b0k = (const float*)d_in[13];
  p.g1k  = (const float*)d_in[14];  p.b1k = (const float*)d_in[15];
  p.g0q  = (const float*)d_in[16];  p.b0q = (const float*)d_in[17];
  p.g1q  = (const float*)d_in[18];  p.b1q = (const float*)d_in[19];
  const float* fx1w = (const float*)d_in[20];  p.fx1b = (const float*)d_in[21];
  const float* fx2w = (const float*)d_in[22];  p.fx2b = (const float*)d_in[23];
  const float* fk1w = (const float*)d_in[24];  p.fk1b = (const float*)d_in[25];
  const float* fk2w = (const float*)d_in[26];  p.fk2b = (const float*)d_in[27];
  const float* fq1w = (const float*)d_in[28];  p.fq1b = (const float*)d_in[29];
  const float* fq2w = (const float*)d_in[30];  p.fq2b = (const float*)d_in[31];

  float* out = (float*)d_out;
  p.K = out;
  p.Q = out + SZ;
  p.V = out + 2 * SZ;

  cudaFuncSetAttribute((const void*)attn_step_kernel,
                       cudaFuncAttributeMaxDynamicSharedMemorySize, SMEM_BYTES);

  // one-time prep: transposed FFN weights + raw projections (+t=0 outputs & KT shadow)
  transpose_w_kernel<<<6, NT>>>(fk1w, fk2w, fq1w, fq2w, fx1w, fx2w);
  precompute_raw_kernel<<<Bn * NUMn * 8, NT>>>(x, emb, Wk, bk, Wq, bq, Wv, bv,
                                               p.K, p.Q, p.V);

  // A(1)
  p.t = 1;
  attn_step_kernel<<<dim3(8, Bn), NT, SMEM_BYTES>>>(p, 0);
  // merged B(t) + A(t+1), t = 1..62  (384 CTAs, no idle blocks)
  for (int t = 1; t <= 62; t++) {
    p.t = t;
    attn_step_kernel<<<dim3(12, Bn), NT, SMEM_BYTES>>>(p, 1);
  }
  // B(63)
  p.t = 63;
  attn_step_kernel<<<dim3(4, Bn), NT, SMEM_BYTES>>>(p, 2);
}

// round 16
// speedup vs baseline: 1.2842x; 1.0023x over previous
#include <cuda_runtime.h>

// ---------------- problem constants ----------------
#define Ln   256
#define Cn   64
#define NUMn 64
#define Bn   32
#define NT   256
#define SA   68    // row stride (floats): 272B % 128 == 16 -> conflict-free LDS.128 phases
#define SV   260   // row stride (floats) for c-major K/V tiles: 1040B % 128 == 16
#define SP   132   // row stride (floats) for P/Q region: 528B % 128 == 16
#define ST   68    // row stride for output-transpose staging tile (mult of 4 -> aligned LDS.128)

#define SZ (33554432ULL)  // B*NUM*L*C per tensor

// gmem scratch (device globals = sanctioned scratch)
__device__ float g_rawQ[SZ];     // raw q projections, row-major [b][t][l][c]
__device__ float g_rawKT[SZ];    // raw k, c-major [b][t][c][l]
__device__ float g_rawQT[SZ];    // raw q, c-major
__device__ float g_rawVT[SZ];    // raw v, c-major
__device__ float g_KT[SZ];       // shadow of output K, c-major
__device__ float g_WT[6 * 4096]; // fk1,fk2,fq1,fq2,fx1,fx2 transposed [c][d]

// ---------------- shared memory layout (floats) ----------------
// OFF_A (17408 fl): Kt[64][SV] -> Vt[64][SV] -> {z,h,W1t,W2t}[64][SA] each
#define OFF_A  0
#define OFF_Z  (OFF_A)
#define OFF_H  (OFF_A + 64*SA)
#define OFF_W1 (OFF_A + 128*SA)
#define OFF_W2 (OFF_A + 192*SA)
#define OFF_P  (OFF_A + 256*SA)   // 64*SP = 8448 fl: Q staging -> P chunk -> out-transpose stage
#define OFF_C  (OFF_P + 64*SP)
#define C_G0   (OFF_C + 0)
#define C_B0   (OFF_C + 64)
#define C_G1   (OFF_C + 128)
#define C_B1   (OFF_C + 192)
#define C_F1B  (OFF_C + 256)
#define C_F2B  (OFF_C + 320)
#define SMEM_FLOATS (OFF_C + 384)
#define SMEM_BYTES  (SMEM_FLOATS * 4)   // 104,960 B -> 2 CTAs/SM

typedef unsigned long long u64t;

__device__ __forceinline__ u64t fma2(u64t a, u64t b, u64t c) {
  u64t d; asm("fma.rn.f32x2 %0, %1, %2, %3;" : "=l"(d) : "l"(a), "l"(b), "l"(c)); return d;
}
__device__ __forceinline__ u64t pack2(float x, float y) {
  u64t d; asm("mov.b64 %0, {%1, %2};" : "=l"(d) : "f"(x), "f"(y)); return d;
}
__device__ __forceinline__ float2 unpack2(u64t v) {
  float2 r; asm("mov.b64 {%0, %1}, %2;" : "=f"(r.x), "=f"(r.y) : "l"(v)); return r;
}
__device__ __forceinline__ float f4c(const float4& v, int k) {
  return (k == 0) ? v.x : (k == 1) ? v.y : (k == 2) ? v.z : v.w;
}

struct AttnParams {
  const float *g0x, *b0x, *g1x, *b1x;
  const float *g0k, *b0k, *g1k, *b1k;
  const float *g0q, *b0q, *g1q, *b1q;
  const float *fx1b, *fx2b, *fk1b, *fk2b, *fq1b, *fq2b;
  float *K, *Q, *V;
  int t;
};

__device__ __forceinline__ float hmax16(float v) {
  v = fmaxf(v, __shfl_xor_sync(0xffffffffu, v, 1));
  v = fmaxf(v, __shfl_xor_sync(0xffffffffu, v, 2));
  v = fmaxf(v, __shfl_xor_sync(0xffffffffu, v, 4));
  v = fmaxf(v, __shfl_xor_sync(0xffffffffu, v, 8));
  return v;
}
__device__ __forceinline__ float hsum16(float v) {
  v += __shfl_xor_sync(0xffffffffu, v, 1);
  v += __shfl_xor_sync(0xffffffffu, v, 2);
  v += __shfl_xor_sync(0xffffffffu, v, 4);
  v += __shfl_xor_sync(0xffffffffu, v, 8);
  return v;
}

// coalesced row-copy: gmem [64][256] (c-major) -> smem [64][SV]
__device__ __forceinline__ void load_cmajor_64x256(float* dst, const float* __restrict__ src, int tid) {
  const float4* s4 = (const float4*)src;
  #pragma unroll
  for (int it = 0; it < 16; it++) {
    int i = tid + it * NT;          // 0..4095
    int r = i >> 6, c4 = (i & 63) << 2;
    *(float4*)(dst + r * SV + c4) = __ldg(s4 + i);
  }
}

// coalesced row-copy: gmem [64][64] (already transposed) -> smem [64][SA]
__device__ __forceinline__ void load_cmajor_64x64(float* dst, const float* __restrict__ src, int tid) {
  const float4* s4 = (const float4*)src;
  #pragma unroll
  for (int it = 0; it < 4; it++) {
    int i = tid + it * NT;          // 0..1023
    int r = i >> 4, c4 = (i & 15) << 2;
    *(float4*)(dst + r * SA + c4) = __ldg(s4 + i);
  }
}

// ============ one-time: transpose the 6 FFN weight matrices into g_WT ============
__global__ __launch_bounds__(NT)
void transpose_w_kernel(const float* s0, const float* s1, const float* s2,
                        const float* s3, const float* s4, const float* s5) {
  __shared__ float tile[64][65];
  const float* srcs[6] = {s0, s1, s2, s3, s4, s5};
  const float* src = srcs[blockIdx.x];
  float* dst = g_WT + blockIdx.x * 4096;
  const int tid = threadIdx.x;
  for (int i = tid; i < 4096; i += NT) tile[i >> 6][i & 63] = __ldg(src + i);
  __syncthreads();
  for (int i = tid; i < 4096; i += NT) dst[i] = tile[i & 63][i >> 6];
}

// ============ precompute: raw projections (+transposed variants); K/Q/V & KT at t=0 ============
// grid = Bn*NUMn*8; block covers one (b,t) 32-row slab (l0..l0+31) x 8 heads
__global__ __launch_bounds__(NT)
void precompute_raw_kernel(const float* __restrict__ x, const float* __restrict__ emb,
                           const float* __restrict__ Wk, const float* __restrict__ bk,
                           const float* __restrict__ Wq, const float* __restrict__ bq,
                           const float* __restrict__ Wv, const float* __restrict__ bv,
                           float* __restrict__ K, float* __restrict__ Q, float* __restrict__ V) {
  __shared__ float w[3 * 512 + 3 * 64];
  __shared__ float tr[3][64][33];
  const int tid = threadIdx.x;
  for (int i = tid; i < 512; i += NT) {
    w[i]        = __ldg(Wk + i);
    w[512 + i]  = __ldg(Wq + i);
    w[1024 + i] = __ldg(Wv + i);
  }
  if (tid < 64) {
    w[1536 + tid] = __ldg(bk + tid);
    w[1600 + tid] = __ldg(bq + tid);
    w[1664 + tid] = __ldg(bv + tid);
  }
  __syncthreads();

  const int bidx  = blockIdx.x;
  const int btIdx = bidx >> 3;          // b*64 + t
  const int l0    = (bidx & 7) << 5;
  const int t     = btIdx & 63;
  const int h  = tid & 7;
  const int dl = tid >> 3;              // 0..31
  const int l  = l0 + dl;
  const size_t row = (size_t)btIdx * 256 + l;

  float xe[8];
  const float* xr = x + row * 64 + h * 8;
  const float* er = emb + l * 64 + h * 8;
  #pragma unroll
  for (int d = 0; d < 8; d++) xe[d] = __ldg(xr + d) + __ldg(er + d);

  float* outs0[3] = {K, Q, V};
  #pragma unroll
  for (int pidx = 0; pidx < 3; pidx++) {
    const float* W  = w + pidx * 512 + h * 64;
    const float* bb = w + 1536 + pidx * 64 + h * 8;
    float acc[8];
    #pragma unroll
    for (int e = 0; e < 8; e++) acc[e] = bb[e];
    #pragma unroll
    for (int d = 0; d < 8; d++) {
      float xv = xe[d];
      #pragma unroll
      for (int e = 0; e < 8; e++) acc[e] = fmaf(xv, W[d * 8 + e], acc[e]);
    }
    #pragma unroll
    for (int e = 0; e < 8; e++) tr[pidx][h * 8 + e][dl] = acc[e];
    if (pidx == 1) {
      float* dq = g_rawQ + row * 64 + h * 8;
      #pragma unroll
      for (int e = 0; e < 8; e++) dq[e] = acc[e];
    }
    if (t == 0) {
      float* d2 = outs0[pidx] + row * 64 + h * 8;
      #pragma unroll
      for (int e = 0; e < 8; e++) d2[e] = acc[e];
    }
  }
  __syncthreads();

  // coalesced transposed writes: [c][l] slab
  const size_t base = (size_t)btIdx * 16384;
  for (int j = tid; j < 2048; j += NT) {
    int c = j >> 5, d = j & 31;
    size_t off = base + (size_t)c * 256 + l0 + d;
    g_rawKT[off] = tr[0][c][d];
    g_rawQT[off] = tr[1][c][d];
    g_rawVT[off] = tr[2][c][d];
    if (t == 0) g_KT[off] = tr[0][c][d];
  }
}

// ============ attention body (RPT=4 rows/thread; RB=64 rows per CTA) ============
// mode 0: k-attn  keysT=rawKT[t], vals=keys tile, queries=Q[t-1]  -> K[t] (+KT shadow, staged)
// mode 1: q-attn  keysT=KT[t-1],  valsT=rawQT[t], queries=rawQ[t] -> Q[t]
// mode 2: v-attn  keysT=KT[t],    valsT=rawVT[t], queries=Q[t]    -> V[t]
template <int RPT>
__device__ __forceinline__ void attn_body(const AttnParams& p, int mode, int t, int rb, float* sm) {
  const int tid = threadIdx.x;
  const int b   = blockIdx.y;

  const size_t bOff    = (size_t)b * NUMn * Ln * Cn;
  const size_t curOff  = bOff + (size_t)t * Ln * Cn;
  const size_t prevOff = bOff + (size_t)(t - 1) * Ln * Cn;

  const float *g0, *b0, *g1, *b1, *fb1, *fb2;
  const float *keysT, *qG, *valsT, *w1, *w2;
  float* outG;
  if (mode == 0) {
    g0 = p.g0k; b0 = p.b0k; g1 = p.g1k; b1 = p.b1k;
    fb1 = p.fk1b; fb2 = p.fk2b;
    w1 = g_WT + 0 * 4096; w2 = g_WT + 1 * 4096;
    keysT = g_rawKT + curOff; valsT = 0;   // vals == keys tile
    qG = p.Q + prevOff + (size_t)rb * Cn;
    outG = p.K + curOff;
  } else if (mode == 1) {
    g0 = p.g0q; b0 = p.b0q; g1 = p.g1q; b1 = p.b1q;
    fb1 = p.fq1b; fb2 = p.fq2b;
    w1 = g_WT + 2 * 4096; w2 = g_WT + 3 * 4096;
    keysT = g_KT + prevOff; valsT = g_rawQT + curOff;
    qG = g_rawQ + curOff + (size_t)rb * Cn;
    outG = p.Q + curOff;
  } else {
    g0 = p.g0x; b0 = p.b0x; g1 = p.g1x; b1 = p.b1x;
    fb1 = p.fx1b; fb2 = p.fx2b;
    w1 = g_WT + 4 * 4096; w2 = g_WT + 5 * 4096;
    keysT = g_KT + curOff; valsT = g_rawVT + curOff;
    qG = p.Q + curOff + (size_t)rb * Cn;
    outG = p.V + curOff;
  }

  // ---- load Kt (coalesced, pre-transposed), Q rows (stride SP), consts ----
  load_cmajor_64x256(sm + OFF_A, keysT, tid);
  {
    const float4* q4 = (const float4*)qG;
    #pragma unroll
    for (int it = 0; it < RPT; it++) {
      int i = tid + it * NT;
      float4 v = __ldg(q4 + i);
      int l = i >> 4, c = (i & 15) << 2;
      *(float4*)(sm + OFF_P + l * SP + c) = v;
    }
    if (tid < 64) {
      sm[C_G0  + tid] = __ldg(g0 + tid);
      sm[C_B0  + tid] = __ldg(b0 + tid);
      sm[C_G1  + tid] = __ldg(g1 + tid);
      sm[C_B1  + tid] = __ldg(b1 + tid);
      sm[C_F1B + tid] = __ldg(fb1 + tid);
      sm[C_F2B + tid] = __ldg(fb2 + tid);
    }
  }
  __syncthreads();

  const int rg = tid >> 4;   // 16 row-groups, RPT rows each
  const int cg = tid & 15;   // thread owns S cols 4*cg + 64*q + e  (q=0..3, e=0..3)

  // ---- S = Q @ Kt (RB x 256, k=64), packed f32x2 along n ----
  u64t acc[RPT][4][2];
  #pragma unroll
  for (int i = 0; i < RPT; i++)
    #pragma unroll
    for (int q = 0; q < 4; q++) { acc[i][q][0] = 0ull; acc[i][q][1] = 0ull; }
  {
    const float* qb = sm + OFF_P + (rg * RPT) * SP;
    #pragma unroll 4
    for (int d4 = 0; d4 < 64; d4 += 4) {
      float4 qv[RPT];
      #pragma unroll
      for (int i = 0; i < RPT; i++) qv[i] = *(const float4*)(qb + i * SP + d4);
      #pragma unroll
      for (int dd = 0; dd < 4; dd++) {
        u64t qp[RPT];
        #pragma unroll
        for (int i = 0; i < RPT; i++) { float s = f4c(qv[i], dd); qp[i] = pack2(s, s); }
        const float* kt = sm + OFF_A + (d4 + dd) * SV + 4 * cg;
        #pragma unroll
        for (int q = 0; q < 4; q++) {
          ulonglong2 kv = *(const ulonglong2*)(kt + 64 * q);
          #pragma unroll
          for (int i = 0; i < RPT; i++) {
            acc[i][q][0] = fma2(qp[i], kv.x, acc[i][q][0]);
            acc[i][q][1] = fma2(qp[i], kv.y, acc[i][q][1]);
          }
        }
      }
    }
  }
  __syncthreads();  // Kt + Q reads done; A region free

  // ---- load Vt into A (coalesced; skipped for mode 0 where vals == keys tile) ----
  if (mode != 0) load_cmajor_64x256(sm + OFF_A, valsT, tid);

  // ---- softmax in registers, fold /sqrt(64) ----
  float pv[RPT][16];
  #pragma unroll
  for (int i = 0; i < RPT; i++) {
    #pragma unroll
    for (int q = 0; q < 4; q++) {
      float2 e0 = unpack2(acc[i][q][0]);
      float2 e1 = unpack2(acc[i][q][1]);
      pv[i][q * 4 + 0] = e0.x; pv[i][q * 4 + 1] = e0.y;
      pv[i][q * 4 + 2] = e1.x; pv[i][q * 4 + 3] = e1.y;
    }
    float m = pv[i][0];
    #pragma unroll
    for (int j = 1; j < 16; j++) m = fmaxf(m, pv[i][j]);
    m = hmax16(m);
    float s = 0.f;
    #pragma unroll
    for (int j = 0; j < 16; j++) {
      float e = __expf(pv[i][j] - m);
      pv[i][j] = e;
      s += e;
    }
    s = hsum16(s);
    float sc = 0.125f / s;
    #pragma unroll
    for (int j = 0; j < 16; j++) pv[i][j] *= sc;
  }

  // ---- O = P @ V, k in 2 chunks of 128 via smem P tile (dead Q region) ----
  u64t acc2[RPT][4];
  #pragma unroll
  for (int i = 0; i < RPT; i++)
    #pragma unroll
    for (int c2 = 0; c2 < 4; c2++) acc2[i][c2] = 0ull;
  #pragma unroll
  for (int ch = 0; ch < 2; ch++) {
    __syncthreads();  // ch0: Vt stores + Q reads complete; ch1: chunk-0 reads complete
    #pragma unroll
    for (int i = 0; i < RPT; i++) {
      float* pr = sm + OFF_P + (rg * RPT + i) * SP;
      *(float4*)(pr + 4 * cg) =
          make_float4(pv[i][(2*ch)*4 + 0], pv[i][(2*ch)*4 + 1], pv[i][(2*ch)*4 + 2], pv[i][(2*ch)*4 + 3]);
      *(float4*)(pr + 64 + 4 * cg) =
          make_float4(pv[i][(2*ch+1)*4 + 0], pv[i][(2*ch+1)*4 + 1], pv[i][(2*ch+1)*4 + 2], pv[i][(2*ch+1)*4 + 3]);
    }
    __syncthreads();  // chunk visible
    const float* pb = sm + OFF_P + (rg * RPT) * SP;
    const float* vb = sm + OFF_A + cg * SV + ch * 128;
    #pragma unroll 4
    for (int m4 = 0; m4 < 128; m4 += 4) {
      ulonglong2 pp[RPT];
      #pragma unroll
      for (int i = 0; i < RPT; i++) pp[i] = *(const ulonglong2*)(pb + i * SP + m4);
      #pragma unroll
      for (int c2 = 0; c2 < 4; c2++) {
        ulonglong2 vv = *(const ulonglong2*)(vb + c2 * (16 * SV) + m4);
        #pragma unroll
        for (int i = 0; i < RPT; i++) {
          acc2[i][c2] = fma2(pp[i].x, vv.x, acc2[i][c2]);
          acc2[i][c2] = fma2(pp[i].y, vv.y, acc2[i][c2]);
        }
      }
    }
  }

  // ---- residual (+v at query row) + LayerNorm 1 ----
  float z[RPT][4];
  {
    float sum[RPT], sq[RPT];
    #pragma unroll
    for (int i = 0; i < RPT; i++) { sum[i] = 0.f; sq[i] = 0.f; }
    #pragma unroll
    for (int i = 0; i < RPT; i++) {
      int n = rb + rg * RPT + i;
      #pragma unroll
      for (int c2 = 0; c2 < 4; c2++) {
        float2 tacc = unpack2(acc2[i][c2]);
        float o = tacc.x + tacc.y + sm[OFF_A + (cg + 16 * c2) * SV + n];
        z[i][c2] = o;
        sum[i] += o;
        sq[i]  += o * o;
      }
    }
    #pragma unroll
    for (int i = 0; i < RPT; i++) { sum[i] = hsum16(sum[i]); sq[i] = hsum16(sq[i]); }
    #pragma unroll
    for (int i = 0; i < RPT; i++) {
      float mean = sum[i] * (1.f / 64.f);
      float var  = sq[i] * (1.f / 64.f) - mean * mean;
      float rs = rsqrtf(var + 1e-5f);
      #pragma unroll
      for (int c2 = 0; c2 < 4; c2++) {
        int c = cg + 16 * c2;
        z[i][c2] = (z[i][c2] - mean) * rs * sm[C_G0 + c] + sm[C_B0 + c];
      }
    }
  }
  __syncthreads();  // Vt + P dead; A region free

  // ---- stage z; load W1t,W2t (pre-transposed, coalesced) ----
  #pragma unroll
  for (int i = 0; i < RPT; i++)
    #pragma unroll
    for (int c2 = 0; c2 < 4; c2++)
      sm[OFF_Z + (rg * RPT + i) * SA + cg + 16 * c2] = z[i][c2];
  load_cmajor_64x64(sm + OFF_W1, w1, tid);
  load_cmajor_64x64(sm + OFF_W2, w2, tid);
  __syncthreads();

  // ---- FFN layer 1: h = relu(z @ W1 + b1), packed f32x2 along k ----
  {
    u64t hacc[RPT][4];
    #pragma unroll
    for (int i = 0; i < RPT; i++)
      #pragma unroll
      for (int c2 = 0; c2 < 4; c2++) hacc[i][c2] = 0ull;
    const float* zb = sm + OFF_Z + (rg * RPT) * SA;
    const float* wb = sm + OFF_W1 + cg * SA;
    #pragma unroll 4
    for (int d4 = 0; d4 < 64; d4 += 4) {
      ulonglong2 zz[RPT];
      #pragma unroll
      for (int i = 0; i < RPT; i++) zz[i] = *(const ulonglong2*)(zb + i * SA + d4);
      #pragma unroll
      for (int c2 = 0; c2 < 4; c2++) {
        ulonglong2 ww = *(const ulonglong2*)(wb + c2 * (16 * SA) + d4);
        #pragma unroll
        for (int i = 0; i < RPT; i++) {
          hacc[i][c2] = fma2(zz[i].x, ww.x, hacc[i][c2]);
          hacc[i][c2] = fma2(zz[i].y, ww.y, hacc[i][c2]);
        }
      }
    }
    #pragma unroll
    for (int i = 0; i < RPT; i++)
      #pragma unroll
      for (int c2 = 0; c2 < 4; c2++) {
        float2 th = unpack2(hacc[i][c2]);
        float hv = th.x + th.y + sm[C_F1B + cg + 16 * c2];
        sm[OFF_H + (rg * RPT + i) * SA + cg + 16 * c2] = fmaxf(hv, 0.f);
      }
  }
  __syncthreads();

  // ---- FFN layer 2 + residual + LayerNorm 2 + store (+staged KT shadow for mode 0) ----
  {
    u64t facc[RPT][4];
    #pragma unroll
    for (int i = 0; i < RPT; i++)
      #pragma unroll
      for (int c2 = 0; c2 < 4; c2++) facc[i][c2] = 0ull;
    const float* hb = sm + OFF_H + (rg * RPT) * SA;
    const float* wb = sm + OFF_W2 + cg * SA;
    #pragma unroll 4
    for (int d4 = 0; d4 < 64; d4 += 4) {
      ulonglong2 hh[RPT];
      #pragma unroll
      for (int i = 0; i < RPT; i++) hh[i] = *(const ulonglong2*)(hb + i * SA + d4);
      #pragma unroll
      for (int c2 = 0; c2 < 4; c2++) {
        ulonglong2 ww = *(const ulonglong2*)(wb + c2 * (16 * SA) + d4);
        #pragma unroll
        for (int i = 0; i < RPT; i++) {
          facc[i][c2] = fma2(hh[i].x, ww.x, facc[i][c2]);
          facc[i][c2] = fma2(hh[i].y, ww.y, facc[i][c2]);
        }
      }
    }
    float f[RPT][4];
    float sum[RPT], sq[RPT];
    #pragma unroll
    for (int i = 0; i < RPT; i++) { sum[i] = 0.f; sq[i] = 0.f; }
    #pragma unroll
    for (int i = 0; i < RPT; i++)
      #pragma unroll
      for (int c2 = 0; c2 < 4; c2++) {
        float2 tf = unpack2(facc[i][c2]);
        float o = tf.x + tf.y + sm[C_F2B + cg + 16 * c2] + z[i][c2];
        f[i][c2] = o;
        sum[i] += o;
        sq[i]  += o * o;
      }
    #pragma unroll
    for (int i = 0; i < RPT; i++) { sum[i] = hsum16(sum[i]); sq[i] = hsum16(sq[i]); }
    #pragma unroll
    for (int i = 0; i < RPT; i++) {
      float mean = sum[i] * (1.f / 64.f);
      float var  = sq[i] * (1.f / 64.f) - mean * mean;
      float rs = rsqrtf(var + 1e-5f);
      int n = rg * RPT + i;
      float* orow = outG + (size_t)(rb + n) * Cn;
      #pragma unroll
      for (int c2 = 0; c2 < 4; c2++) {
        int c = cg + 16 * c2;
        float val = (f[i][c2] - mean) * rs * sm[C_G1 + c] + sm[C_B1 + c];
        orow[c] = val;
        if (mode == 0) sm[OFF_P + c * ST + n] = val;  // stage transposed (OFF_P free)
      }
    }
  }

  // ---- mode 0 only: coalesced KT shadow from staged tile ----
  if (mode == 0) {
    __syncthreads();
    float* ktG = g_KT + curOff + rb;      // KT[c][rb + n], row stride 256
    #pragma unroll
    for (int it = 0; it < 4; it++) {
      int i = tid + it * NT;              // 0..1023
      int r = i >> 4, n4 = (i & 15) << 2;
      float4 v = *(const float4*)(sm + OFF_P + r * ST + n4);
      *(float4*)(ktG + (size_t)r * 256 + n4) = v;
    }
  }
}

// job 0: A(t)  grid (8,32): bx>>2 -> mode 0/1 at t, rb=(bx&3)*64
// job 2: B(t)  grid (4,32): mode 2 at t, rb=bx*64
__global__ __launch_bounds__(NT, 2)
void attn_step_kernel(AttnParams p, int job) {
  extern __shared__ float sm[];
  const int bx = (int)blockIdx.x;
  if (job == 0) {
    attn_body<4>(p, bx >> 2, p.t, (bx & 3) * 64, sm);
  } else {
    attn_body<4>(p, 2, p.t, bx * 64, sm);
  }
}

extern "C" void kernel_launch(void* const* d_in, const int* in_sizes, int n_in,
                              void* d_out, int out_size) {
  (void)in_sizes; (void)n_in; (void)out_size;
  const float* x   = (const float*)d_in[0];
  const float* emb = (const float*)d_in[1];
  const float* Wk  = (const float*)d_in[2];
  const float* bk  = (const float*)d_in[3];
  const float* Wq  = (const float*)d_in[4];
  const float* bq  = (const float*)d_in[5];
  const float* Wv  = (const float*)d_in[6];
  const float* bv  = (const float*)d_in[7];

  AttnParams p;
  p.g0x  = (const float*)d_in[8];   p.b0x = (const float*)d_in[9];
  p.g1x  = (const float*)d_in[10];  p.b1x = (const float*)d_in[11];
  p.g0k  = (const float*)d_in[12];  p.b0k = (const float*)d_in[13];
  p.g1k  = (const float*)d_in[14];  p.b1k = (const float*)d_in[15];
  p.g0q  = (const float*)d_in[16];  p.b0q = (const float*)d_in[17];
  p.g1q  = (const float*)d_in[18];  p.b1q = (const float*)d_in[19];
  const float* fx1w = (const float*)d_in[20];  p.fx1b = (const float*)d_in[21];
  const float* fx2w = (const float*)d_in[22];  p.fx2b = (const float*)d_in[23];
  const float* fk1w = (const float*)d_in[24];  p.fk1b = (const float*)d_in[25];
  const float* fk2w = (const float*)d_in[26];  p.fk2b = (const float*)d_in[27];
  const float* fq1w = (const float*)d_in[28];  p.fq1b = (const float*)d_in[29];
  const float* fq2w = (const float*)d_in[30];  p.fq2b = (const float*)d_in[31];

  float* out = (float*)d_out;
  p.K = out;
  p.Q = out + SZ;
  p.V = out + 2 * SZ;

  // persistent side-stream + events (created once; graph replays require them to outlive capture)
  static cudaStream_t s2 = 0;
  static cudaEvent_t evA[NUMn];
  static cudaEvent_t evDone = 0;
  if (s2 == 0) {
    cudaStreamCreateWithFlags(&s2, cudaStreamNonBlocking);
    for (int i = 0; i < NUMn; i++) cudaEventCreateWithFlags(&evA[i], cudaEventDisableTiming);
    cudaEventCreateWithFlags(&evDone, cudaEventDisableTiming);
    cudaFuncSetAttribute((const void*)attn_step_kernel,
                         cudaFuncAttributeMaxDynamicSharedMemorySize, SMEM_BYTES);
  }

  // one-time prep: transposed FFN weights + raw projections (+t=0 outputs & KT shadow)
  transpose_w_kernel<<<6, NT>>>(fk1w, fk2w, fq1w, fq2w, fx1w, fx2w);
  precompute_raw_kernel<<<Bn * NUMn * 8, NT>>>(x, emb, Wk, bk, Wq, bq, Wv, bv,
                                               p.K, p.Q, p.V);

  // critical chain A(1..63) on the main stream; B(t) overlapped on s2 (nothing reads V[t])
  for (int t = 1; t <= 63; t++) {
    p.t = t;
    attn_step_kernel<<<dim3(8, Bn), NT, SMEM_BYTES>>>(p, 0);        // A(t)
    cudaEventRecord(evA[t], 0);
    cudaStreamWaitEvent(s2, evA[t], 0);
    attn_step_kernel<<<dim3(4, Bn), NT, SMEM_BYTES, s2>>>(p, 2);    // B(t)
  }
  cudaEventRecord(evDone, s2);
  cudaStreamWaitEvent(0, evDone, 0);
}